// round 9
// baseline (speedup 1.0000x reference)
#include <cuda_runtime.h>
#include <cuda_fp16.h>
#include <math.h>
#include <stdint.h>

// Problem shape: B=4, S=4096, D=1024, H=64
#define B_ 4
#define S_ 4096
#define D_ 1024
#define H_ 64
#define NROWS (B_ * S_)   // 16384

// Attention operands (fp16). Q UNSCALED (1/sqrt(H) folded into exp2 constant).
__device__ __half g_qh[NROWS * H_];
__device__ __half g_kh[NROWS * H_];
__device__ __half g_vh[NROWS * H_];
// Pre-converted W (fp16) in per-64k-chunk swizzled tile layout (8KB per chunk).
__device__ __half g_wh[3][D_ * H_];
// Split-K partials: unnormalized o and l per half.
__device__ float g_po[2][NROWS * H_];
__device__ float g_pl[2][NROWS];

// ===========================================================================
// helpers
// ===========================================================================
__device__ __forceinline__ uint32_t smem_u32(const void* p) {
    uint32_t a;
    asm("{ .reg .u64 t; cvta.to.shared.u64 t, %1; cvt.u32.u64 %0, t; }" : "=r"(a) : "l"(p));
    return a;
}
__device__ __forceinline__ uint32_t packhf(float a, float b) {
    uint32_t r;
    asm("cvt.rn.f16x2.f32 %0, %2, %1;" : "=r"(r) : "f"(a), "f"(b));
    return r;
}
__device__ __forceinline__ uint32_t pack2h(__half a, __half b) {
    return (uint32_t)__half_as_ushort(a) | ((uint32_t)__half_as_ushort(b) << 16);
}
__device__ __forceinline__ void split2h(float a, float b, uint32_t& hi, uint32_t& lo) {
    __half ha = __float2half_rn(a), hb = __float2half_rn(b);
    hi = pack2h(ha, hb);
    lo = packhf(a - __half2float(ha), b - __half2float(hb));
}
__device__ __forceinline__ float ex2f(float x) {
    float r;
    asm("ex2.approx.f32 %0, %1;" : "=f"(r) : "f"(x));
    return r;
}

__device__ __forceinline__ void ldsm4(uint32_t& r0, uint32_t& r1, uint32_t& r2, uint32_t& r3, uint32_t addr) {
    asm volatile("ldmatrix.sync.aligned.m8n8.x4.shared.b16 {%0,%1,%2,%3}, [%4];"
        : "=r"(r0), "=r"(r1), "=r"(r2), "=r"(r3) : "r"(addr));
}
__device__ __forceinline__ void ldsm4t(uint32_t& r0, uint32_t& r1, uint32_t& r2, uint32_t& r3, uint32_t addr) {
    asm volatile("ldmatrix.sync.aligned.m8n8.x4.trans.shared.b16 {%0,%1,%2,%3}, [%4];"
        : "=r"(r0), "=r"(r1), "=r"(r2), "=r"(r3) : "r"(addr));
}
__device__ __forceinline__ void mma16816h(float& d0, float& d1, float& d2, float& d3,
                                           uint32_t a0, uint32_t a1, uint32_t a2, uint32_t a3,
                                           uint32_t b0, uint32_t b1) {
    asm volatile("mma.sync.aligned.m16n8k16.row.col.f32.f16.f16.f32 "
        "{%0,%1,%2,%3}, {%4,%5,%6,%7}, {%8,%9}, {%0,%1,%2,%3};"
        : "+f"(d0), "+f"(d1), "+f"(d2), "+f"(d3)
        : "r"(a0), "r"(a1), "r"(a2), "r"(a3), "r"(b0), "r"(b1));
}

#define CP_ASYNC16(dst, src) \
    asm volatile("cp.async.cg.shared.global [%0], [%1], 16;" :: "r"(dst), "l"(src))
#define CP_COMMIT() asm volatile("cp.async.commit_group;" ::: "memory")
#define CP_WAIT(n)  asm volatile("cp.async.wait_group %0;" :: "n"(n) : "memory")

// ===========================================================================
// Kernel 0: convert W matrices to fp16, per-chunk swizzled tiles.
// ===========================================================================
__global__ __launch_bounds__(256) void split_w_kernel(
    const float* __restrict__ Wq, const float* __restrict__ Wk, const float* __restrict__ Wv)
{
    const int ck = blockIdx.x, m = blockIdx.y, tid = threadIdx.x;
    const float4* W4 = (const float4*)((m == 0) ? Wq : ((m == 1) ? Wk : Wv));
    char* hiB = (char*)g_wh[m] + ck * 8192;
    #pragma unroll
    for (int j = 0; j < 4; j++) {
        int f = tid + j * 256;
        int r = f >> 4, c4 = f & 15;
        float4 v = W4[(size_t)(ck * 64 + r) * 16 + c4];
        uint32_t so = (uint32_t)(r * 128 + (((c4 >> 1) ^ (r & 7)) << 4) + (c4 & 1) * 8);
        *(uint32_t*)(hiB + so)     = packhf(v.x, v.y);
        *(uint32_t*)(hiB + so + 4) = packhf(v.z, v.w);
    }
}

// ===========================================================================
// Kernel 1: fused QKV projection + LayerNorm, fp16x2 (X hi/lo, W single).
// (unchanged from R8)
// ===========================================================================
#define P_XHI 0
#define P_XLO 16384
#define P_WH  32768
#define P_WSTRIDE 8192
#define PROJ_SMEM (32768 + 3 * 8192)

__global__ __launch_bounds__(256) void proj_ln_kernel(const float* __restrict__ X)
{
    extern __shared__ char smem[];
    const uint32_t sb = smem_u32(smem);
    const int tid  = threadIdx.x;
    const int warp = tid >> 5, lane = tid & 31;
    const int wrow = warp * 16;
    const int mt   = blockIdx.x;

    float a0[3][8], a1[3][8], a2[3][8], a3[3][8];
    #pragma unroll
    for (int m = 0; m < 3; m++)
        #pragma unroll
        for (int nc = 0; nc < 8; nc++) { a0[m][nc]=0.f; a1[m][nc]=0.f; a2[m][nc]=0.f; a3[m][nc]=0.f; }

    const float4* X4 = (const float4*)X;

    const int arow = wrow + (lane & 15);
    const int as7  = arow & 7;
    const int abit = lane >> 4;
    const int krv  = lane & 15;
    const int vbit = lane >> 4;
    const int s7   = lane & 7;

    for (int kk = 0; kk < D_; kk += 64) {
        __syncthreads();

        #pragma unroll
        for (int m = 0; m < 3; m++) {
            const char* srcH = (const char*)g_wh[m] + (kk >> 6) * 8192;
            #pragma unroll
            for (int j = 0; j < 2; j++) {
                int f16 = (tid + j * 256) * 16;
                CP_ASYNC16(sb + P_WH + (uint32_t)(m * P_WSTRIDE) + f16, srcH + f16);
            }
        }
        CP_COMMIT();

        #pragma unroll
        for (int j = 0; j < 8; j++) {
            int f = tid + j * 256;
            int r = f >> 4, c4 = f & 15;
            float4 v = X4[(size_t)(mt * 128 + r) * 256 + (kk >> 2) + c4];
            uint32_t h0, l0, h1, l1;
            split2h(v.x, v.y, h0, l0);
            split2h(v.z, v.w, h1, l1);
            uint32_t so = (uint32_t)(r * 128 + (((c4 >> 1) ^ (r & 7)) << 4) + (c4 & 1) * 8);
            *(uint32_t*)(smem + P_XHI + so)     = h0;
            *(uint32_t*)(smem + P_XHI + so + 4) = h1;
            *(uint32_t*)(smem + P_XLO + so)     = l0;
            *(uint32_t*)(smem + P_XLO + so + 4) = l1;
        }
        CP_WAIT(0);
        __syncthreads();

        uint32_t xh[4][4], xl[4][4];
        #pragma unroll
        for (int kc = 0; kc < 4; kc++) {
            int c16 = 2 * kc + abit;
            uint32_t ad = sb + P_XHI + (uint32_t)(arow * 128) + ((c16 ^ as7) << 4);
            ldsm4(xh[kc][0], xh[kc][1], xh[kc][2], xh[kc][3], ad);
            ldsm4(xl[kc][0], xl[kc][1], xl[kc][2], xl[kc][3], ad + (P_XLO - P_XHI));
        }

        #pragma unroll
        for (int m = 0; m < 3; m++) {
            uint32_t wbase = sb + P_WH + (uint32_t)(m * P_WSTRIDE);
            #pragma unroll
            for (int kc = 0; kc < 4; kc++) {
                #pragma unroll
                for (int ncp = 0; ncp < 4; ncp++) {
                    uint32_t ad = wbase + (uint32_t)((kc * 16 + krv) * 128)
                                + (((2 * ncp + vbit) ^ s7) << 4);
                    uint32_t bh0, bh1, bh2, bh3;
                    ldsm4t(bh0, bh1, bh2, bh3, ad);
                    int n = 2 * ncp;
                    mma16816h(a0[m][n], a1[m][n], a2[m][n], a3[m][n],
                              xh[kc][0], xh[kc][1], xh[kc][2], xh[kc][3], bh0, bh1);
                    mma16816h(a0[m][n], a1[m][n], a2[m][n], a3[m][n],
                              xl[kc][0], xl[kc][1], xl[kc][2], xl[kc][3], bh0, bh1);
                    mma16816h(a0[m][n+1], a1[m][n+1], a2[m][n+1], a3[m][n+1],
                              xh[kc][0], xh[kc][1], xh[kc][2], xh[kc][3], bh2, bh3);
                    mma16816h(a0[m][n+1], a1[m][n+1], a2[m][n+1], a3[m][n+1],
                              xl[kc][0], xl[kc][1], xl[kc][2], xl[kc][3], bh2, bh3);
                }
            }
        }
    }

    const int rA = mt * 128 + wrow + (lane >> 2);
    const int rB = rA + 8;

    #pragma unroll
    for (int m = 0; m < 3; m++) {
        float mu0 = 0.f, mu1 = 0.f, rs0 = 1.f, rs1 = 1.f;
        if (m < 2) {
            float sum0 = 0.f, sum1 = 0.f;
            #pragma unroll
            for (int nc = 0; nc < 8; nc++) {
                sum0 += a0[m][nc] + a1[m][nc];
                sum1 += a2[m][nc] + a3[m][nc];
            }
            sum0 += __shfl_xor_sync(0xffffffffu, sum0, 1);
            sum0 += __shfl_xor_sync(0xffffffffu, sum0, 2);
            sum1 += __shfl_xor_sync(0xffffffffu, sum1, 1);
            sum1 += __shfl_xor_sync(0xffffffffu, sum1, 2);
            mu0 = sum0 * (1.0f / 64.0f);
            mu1 = sum1 * (1.0f / 64.0f);
            float v0 = 0.f, v1 = 0.f;
            #pragma unroll
            for (int nc = 0; nc < 8; nc++) {
                float d00 = a0[m][nc] - mu0, d01 = a1[m][nc] - mu0;
                float d10 = a2[m][nc] - mu1, d11 = a3[m][nc] - mu1;
                v0 += d00 * d00 + d01 * d01;
                v1 += d10 * d10 + d11 * d11;
            }
            v0 += __shfl_xor_sync(0xffffffffu, v0, 1);
            v0 += __shfl_xor_sync(0xffffffffu, v0, 2);
            v1 += __shfl_xor_sync(0xffffffffu, v1, 1);
            v1 += __shfl_xor_sync(0xffffffffu, v1, 2);
            rs0 = rsqrtf(v0 * (1.0f / 64.0f) + 1e-5f);
            rs1 = rsqrtf(v1 * (1.0f / 64.0f) + 1e-5f);
        }

        uint32_t* g32 = (uint32_t*)((m == 0) ? g_qh : ((m == 1) ? g_kh : g_vh));
        #pragma unroll
        for (int nc = 0; nc < 8; nc++) {
            uint32_t hA = packhf((a0[m][nc] - mu0) * rs0, (a1[m][nc] - mu0) * rs0);
            uint32_t hB = packhf((a2[m][nc] - mu1) * rs1, (a3[m][nc] - mu1) * rs1);
            size_t iA = (size_t)rA * 32 + nc * 4 + (lane & 3);
            size_t iB = (size_t)rB * 32 + nc * 4 + (lane & 3);
            g32[iA] = hA;
            g32[iB] = hB;
        }
    }
}

// ===========================================================================
// Kernel 2: flash attention, split-K, high occupancy.
// Grid (256 q-tiles, 2 kv-halves); CTA = 128 threads (4 warps), 64 queries,
// 2048 keys in 32 tiles of 64. smem 32KB (2 stages x (K 8KB + V 8KB)),
// regs <= 128 -> 4 CTAs/SM (16 warps).
// Fixed-reference softmax -> partials (sum p*v, sum p) combine by addition.
// ===========================================================================
#define A_KOFF 0
#define A_VOFF 8192
#define A_STAGE 16384
#define ATTN_SMEM (2 * A_STAGE)
#define NT2 (2048 / 64)

__global__ __launch_bounds__(128, 4) void attn_mma_kernel()
{
    extern __shared__ char smem[];
    const uint32_t sb = smem_u32(smem);
    const int tid  = threadIdx.x;
    const int warp = tid >> 5, lane = tid & 31;
    const int wrow = warp * 16;

    const int qt    = blockIdx.x;           // 0..255
    const int half  = blockIdx.y;           // 0..1
    const int qbase = qt * 64;
    const int b     = qbase / S_;

    // ---- stage Q tile (64 rows) into stage0 K area, grab A fragments ----
    {
        const uint4* qh4 = (const uint4*)((const char*)g_qh + (size_t)qbase * 128);
        #pragma unroll
        for (int j = 0; j < 4; j++) {
            int f = tid + j * 128;              // 0..511 float4
            int r = f >> 3, c = f & 7;
            uint32_t so = r * 128 + ((c ^ (r & 7)) << 4);
            *(uint4*)(smem + A_KOFF + so) = qh4[f];
        }
    }
    __syncthreads();

    uint32_t qf[4][4];
    {
        int arow = wrow + (lane & 15);
        int as7  = arow & 7;
        #pragma unroll
        for (int kc = 0; kc < 4; kc++) {
            int c16 = 2 * kc + (lane >> 4);
            uint32_t ad = sb + A_KOFF + arow * 128 + ((c16 ^ as7) << 4);
            ldsm4(qf[kc][0], qf[kc][1], qf[kc][2], qf[kc][3], ad);
        }
    }
    __syncthreads();

    const char* khB = (const char*)g_kh + (size_t)(b * S_ + half * 2048) * 128;
    const char* vhB = (const char*)g_vh + (size_t)(b * S_ + half * 2048) * 128;

    // prefetch tile 0 -> stage 0 (K 512 float4 + V 512 float4; 4+4 per thread)
    {
        #pragma unroll
        for (int j = 0; j < 4; j++) {
            int f = tid + j * 128;
            int r = f >> 3, c = f & 7;
            uint32_t so = r * 128 + ((c ^ (r & 7)) << 4);
            int gs = f * 16;
            CP_ASYNC16(sb + A_KOFF + so, khB + gs);
            CP_ASYNC16(sb + A_VOFF + so, vhB + gs);
        }
        CP_COMMIT();
    }

    float s0[8], s1[8], s2[8], s3[8];
    float o0[8], o1[8], o2[8], o3[8];
    #pragma unroll
    for (int i = 0; i < 8; i++) { o0[i] = 0.f; o1[i] = 0.f; o2[i] = 0.f; o3[i] = 0.f; }
    float l0 = 0.f, l1 = 0.f;

    const int s7   = lane & 7;
    const int krq  = (lane & 7) + ((lane >> 4) << 3);
    const int cbit = (lane >> 3) & 1;
    const int krv  = lane & 15;
    const int vbit = lane >> 4;
    const float C = 0.125f * 1.44269504088896f;   // exp(0.125 s) = 2^(s*C)

    for (int kt = 0; kt < NT2; kt++) {
        __syncthreads();

        if (kt + 1 < NT2) {
            uint32_t dst = sb + ((kt + 1) & 1) * A_STAGE;
            size_t gb = (size_t)((kt + 1) * 64) * 128;
            #pragma unroll
            for (int j = 0; j < 4; j++) {
                int f = tid + j * 128;
                int r = f >> 3, c = f & 7;
                uint32_t so = r * 128 + ((c ^ (r & 7)) << 4);
                size_t gs = gb + f * 16;
                CP_ASYNC16(dst + A_KOFF + so, khB + gs);
                CP_ASYNC16(dst + A_VOFF + so, vhB + gs);
            }
            CP_COMMIT();
            CP_WAIT(1);
        } else {
            CP_WAIT(0);
        }
        __syncthreads();

        const uint32_t bufb = sb + (kt & 1) * A_STAGE;

        // ---- S = Q K^T (64 keys) ----
        #pragma unroll
        for (int i = 0; i < 8; i++) { s0[i] = 0.f; s1[i] = 0.f; s2[i] = 0.f; s3[i] = 0.f; }
        #pragma unroll
        for (int kc = 0; kc < 4; kc++) {
            #pragma unroll
            for (int ncp = 0; ncp < 4; ncp++) {
                uint32_t ad = bufb + A_KOFF + (uint32_t)(ncp * 16 + krq) * 128
                            + (((2 * kc + cbit) ^ s7) << 4);
                uint32_t bh0, bh1, bh2, bh3;
                ldsm4(bh0, bh1, bh2, bh3, ad);
                int n = 2 * ncp;
                mma16816h(s0[n], s1[n], s2[n], s3[n], qf[kc][0], qf[kc][1], qf[kc][2], qf[kc][3], bh0, bh1);
                mma16816h(s0[n+1], s1[n+1], s2[n+1], s3[n+1], qf[kc][0], qf[kc][1], qf[kc][2], qf[kc][3], bh2, bh3);
            }
        }

        // ---- p = exp2(s*C); accumulate l (fixed reference, no max) ----
        #pragma unroll
        for (int i = 0; i < 8; i++) {
            s0[i] = ex2f(s0[i] * C); s1[i] = ex2f(s1[i] * C);
            s2[i] = ex2f(s2[i] * C); s3[i] = ex2f(s3[i] * C);
            l0 += s0[i] + s1[i];
            l1 += s2[i] + s3[i];
        }

        // ---- O += P V ----
        #pragma unroll
        for (int kc = 0; kc < 4; kc++) {
            uint32_t ph0 = packhf(s0[2*kc],   s1[2*kc]);
            uint32_t ph1 = packhf(s2[2*kc],   s3[2*kc]);
            uint32_t ph2 = packhf(s0[2*kc+1], s1[2*kc+1]);
            uint32_t ph3 = packhf(s2[2*kc+1], s3[2*kc+1]);
            #pragma unroll
            for (int ncp = 0; ncp < 4; ncp++) {
                uint32_t ad = bufb + A_VOFF + (uint32_t)(kc * 16 + krv) * 128
                            + (((2 * ncp + vbit) ^ s7) << 4);
                uint32_t bh0, bh1, bh2, bh3;
                ldsm4t(bh0, bh1, bh2, bh3, ad);
                int n = 2 * ncp;
                mma16816h(o0[n], o1[n], o2[n], o3[n], ph0, ph1, ph2, ph3, bh0, bh1);
                mma16816h(o0[n+1], o1[n+1], o2[n+1], o3[n+1], ph0, ph1, ph2, ph3, bh2, bh3);
            }
        }
    }

    // ---- reduce l across quad; store partial o (unnormalized) and l ----
    l0 += __shfl_xor_sync(0xffffffffu, l0, 1);
    l0 += __shfl_xor_sync(0xffffffffu, l0, 2);
    l1 += __shfl_xor_sync(0xffffffffu, l1, 1);
    l1 += __shfl_xor_sync(0xffffffffu, l1, 2);

    const int r  = lane >> 2;
    const int c2 = (lane & 3) * 2;
    float2* po2 = (float2*)g_po[half];
    #pragma unroll
    for (int nc = 0; nc < 8; nc++) {
        size_t i_lo = ((size_t)(qbase + wrow + r)     * 64 + 8 * nc + c2) >> 1;
        size_t i_hi = ((size_t)(qbase + wrow + r + 8) * 64 + 8 * nc + c2) >> 1;
        po2[i_lo] = make_float2(o0[nc], o1[nc]);
        po2[i_hi] = make_float2(o2[nc], o3[nc]);
    }
    if ((lane & 3) == 0) {
        g_pl[half][qbase + wrow + r]     = l0;
        g_pl[half][qbase + wrow + r + 8] = l1;
    }
}

// ===========================================================================
// Kernel 3: combine split-K partials: out = (o0+o1)/(l0+l1).
// ===========================================================================
__global__ __launch_bounds__(256) void combine_kernel(float* __restrict__ out)
{
    int f = blockIdx.x * 256 + threadIdx.x;        // float2 index, 524288 total
    const float2* p0 = (const float2*)g_po[0];
    const float2* p1 = (const float2*)g_po[1];
    float2* o2 = (float2*)out;
    int row = f >> 5;                              // 32 float2 per row of 64
    float inv = 1.0f / (g_pl[0][row] + g_pl[1][row]);
    float2 a = p0[f], bb = p1[f];
    o2[f] = make_float2((a.x + bb.x) * inv, (a.y + bb.y) * inv);
}

// ===========================================================================
// Launch
// ===========================================================================
extern "C" void kernel_launch(void* const* d_in, const int* in_sizes, int n_in,
                              void* d_out, int out_size)
{
    const float* X  = (const float*)d_in[0];
    const float* Wq = (const float*)d_in[1];
    const float* Wk = (const float*)d_in[2];
    const float* Wv = (const float*)d_in[3];
    float* out = (float*)d_out;

    dim3 gw(16, 3);
    split_w_kernel<<<gw, 256>>>(Wq, Wk, Wv);

    cudaFuncSetAttribute(proj_ln_kernel, cudaFuncAttributeMaxDynamicSharedMemorySize, PROJ_SMEM);
    proj_ln_kernel<<<NROWS / 128, 256, PROJ_SMEM>>>(X);

    cudaFuncSetAttribute(attn_mma_kernel, cudaFuncAttributeMaxDynamicSharedMemorySize, ATTN_SMEM);
    dim3 ga(NROWS / 64, 2);
    attn_mma_kernel<<<ga, 128, ATTN_SMEM>>>();

    combine_kernel<<<NROWS * H_ / 512, 256>>>(out);
}

// round 10
// speedup vs baseline: 1.2720x; 1.2720x over previous
#include <cuda_runtime.h>
#include <cuda_fp16.h>
#include <math.h>
#include <stdint.h>

// Problem shape: B=4, S=4096, D=1024, H=64
#define B_ 4
#define S_ 4096
#define D_ 1024
#define H_ 64
#define NROWS (B_ * S_)   // 16384

// Attention operands (fp16). Q UNSCALED (1/sqrt(H) folded into exp2 constant).
__device__ __half g_qh[NROWS * H_];
__device__ __half g_kh[NROWS * H_];
__device__ __half g_vh[NROWS * H_];
// Pre-converted W (fp16) in per-64k-chunk swizzled tile layout (8KB per chunk).
__device__ __half g_wh[3][D_ * H_];

// ===========================================================================
// helpers
// ===========================================================================
__device__ __forceinline__ uint32_t smem_u32(const void* p) {
    uint32_t a;
    asm("{ .reg .u64 t; cvta.to.shared.u64 t, %1; cvt.u32.u64 %0, t; }" : "=r"(a) : "l"(p));
    return a;
}
__device__ __forceinline__ uint32_t packhf(float a, float b) {
    uint32_t r;
    asm("cvt.rn.f16x2.f32 %0, %2, %1;" : "=r"(r) : "f"(a), "f"(b));
    return r;
}
__device__ __forceinline__ uint32_t pack2h(__half a, __half b) {
    return (uint32_t)__half_as_ushort(a) | ((uint32_t)__half_as_ushort(b) << 16);
}
__device__ __forceinline__ void split2h(float a, float b, uint32_t& hi, uint32_t& lo) {
    __half ha = __float2half_rn(a), hb = __float2half_rn(b);
    hi = pack2h(ha, hb);
    lo = packhf(a - __half2float(ha), b - __half2float(hb));
}
__device__ __forceinline__ float ex2f(float x) {
    float r;
    asm("ex2.approx.f32 %0, %1;" : "=f"(r) : "f"(x));
    return r;
}

__device__ __forceinline__ void ldsm4(uint32_t& r0, uint32_t& r1, uint32_t& r2, uint32_t& r3, uint32_t addr) {
    asm volatile("ldmatrix.sync.aligned.m8n8.x4.shared.b16 {%0,%1,%2,%3}, [%4];"
        : "=r"(r0), "=r"(r1), "=r"(r2), "=r"(r3) : "r"(addr));
}
__device__ __forceinline__ void ldsm4t(uint32_t& r0, uint32_t& r1, uint32_t& r2, uint32_t& r3, uint32_t addr) {
    asm volatile("ldmatrix.sync.aligned.m8n8.x4.trans.shared.b16 {%0,%1,%2,%3}, [%4];"
        : "=r"(r0), "=r"(r1), "=r"(r2), "=r"(r3) : "r"(addr));
}
__device__ __forceinline__ void mma16816h(float& d0, float& d1, float& d2, float& d3,
                                           uint32_t a0, uint32_t a1, uint32_t a2, uint32_t a3,
                                           uint32_t b0, uint32_t b1) {
    asm volatile("mma.sync.aligned.m16n8k16.row.col.f32.f16.f16.f32 "
        "{%0,%1,%2,%3}, {%4,%5,%6,%7}, {%8,%9}, {%0,%1,%2,%3};"
        : "+f"(d0), "+f"(d1), "+f"(d2), "+f"(d3)
        : "r"(a0), "r"(a1), "r"(a2), "r"(a3), "r"(b0), "r"(b1));
}

#define CP_ASYNC16(dst, src) \
    asm volatile("cp.async.cg.shared.global [%0], [%1], 16;" :: "r"(dst), "l"(src))
#define CP_COMMIT() asm volatile("cp.async.commit_group;" ::: "memory")
#define CP_WAIT(n)  asm volatile("cp.async.wait_group %0;" :: "n"(n) : "memory")

// ===========================================================================
// Kernel 0: convert W matrices to fp16, per-chunk swizzled tiles.
// ===========================================================================
__global__ __launch_bounds__(256) void split_w_kernel(
    const float* __restrict__ Wq, const float* __restrict__ Wk, const float* __restrict__ Wv)
{
    const int ck = blockIdx.x, m = blockIdx.y, tid = threadIdx.x;
    const float4* W4 = (const float4*)((m == 0) ? Wq : ((m == 1) ? Wk : Wv));
    char* hiB = (char*)g_wh[m] + ck * 8192;
    #pragma unroll
    for (int j = 0; j < 4; j++) {
        int f = tid + j * 256;
        int r = f >> 4, c4 = f & 15;
        float4 v = W4[(size_t)(ck * 64 + r) * 16 + c4];
        uint32_t so = (uint32_t)(r * 128 + (((c4 >> 1) ^ (r & 7)) << 4) + (c4 & 1) * 8);
        *(uint32_t*)(hiB + so)     = packhf(v.x, v.y);
        *(uint32_t*)(hiB + so + 4) = packhf(v.z, v.w);
    }
}

// ===========================================================================
// Kernel 1: fused QKV projection + LayerNorm, fp16x2 (X hi/lo, W single).
// (unchanged from R8)
// ===========================================================================
#define P_XHI 0
#define P_XLO 16384
#define P_WH  32768
#define P_WSTRIDE 8192
#define PROJ_SMEM (32768 + 3 * 8192)

__global__ __launch_bounds__(256) void proj_ln_kernel(const float* __restrict__ X)
{
    extern __shared__ char smem[];
    const uint32_t sb = smem_u32(smem);
    const int tid  = threadIdx.x;
    const int warp = tid >> 5, lane = tid & 31;
    const int wrow = warp * 16;
    const int mt   = blockIdx.x;

    float a0[3][8], a1[3][8], a2[3][8], a3[3][8];
    #pragma unroll
    for (int m = 0; m < 3; m++)
        #pragma unroll
        for (int nc = 0; nc < 8; nc++) { a0[m][nc]=0.f; a1[m][nc]=0.f; a2[m][nc]=0.f; a3[m][nc]=0.f; }

    const float4* X4 = (const float4*)X;

    const int arow = wrow + (lane & 15);
    const int as7  = arow & 7;
    const int abit = lane >> 4;
    const int krv  = lane & 15;
    const int vbit = lane >> 4;
    const int s7   = lane & 7;

    for (int kk = 0; kk < D_; kk += 64) {
        __syncthreads();

        #pragma unroll
        for (int m = 0; m < 3; m++) {
            const char* srcH = (const char*)g_wh[m] + (kk >> 6) * 8192;
            #pragma unroll
            for (int j = 0; j < 2; j++) {
                int f16 = (tid + j * 256) * 16;
                CP_ASYNC16(sb + P_WH + (uint32_t)(m * P_WSTRIDE) + f16, srcH + f16);
            }
        }
        CP_COMMIT();

        #pragma unroll
        for (int j = 0; j < 8; j++) {
            int f = tid + j * 256;
            int r = f >> 4, c4 = f & 15;
            float4 v = X4[(size_t)(mt * 128 + r) * 256 + (kk >> 2) + c4];
            uint32_t h0, l0, h1, l1;
            split2h(v.x, v.y, h0, l0);
            split2h(v.z, v.w, h1, l1);
            uint32_t so = (uint32_t)(r * 128 + (((c4 >> 1) ^ (r & 7)) << 4) + (c4 & 1) * 8);
            *(uint32_t*)(smem + P_XHI + so)     = h0;
            *(uint32_t*)(smem + P_XHI + so + 4) = h1;
            *(uint32_t*)(smem + P_XLO + so)     = l0;
            *(uint32_t*)(smem + P_XLO + so + 4) = l1;
        }
        CP_WAIT(0);
        __syncthreads();

        uint32_t xh[4][4], xl[4][4];
        #pragma unroll
        for (int kc = 0; kc < 4; kc++) {
            int c16 = 2 * kc + abit;
            uint32_t ad = sb + P_XHI + (uint32_t)(arow * 128) + ((c16 ^ as7) << 4);
            ldsm4(xh[kc][0], xh[kc][1], xh[kc][2], xh[kc][3], ad);
            ldsm4(xl[kc][0], xl[kc][1], xl[kc][2], xl[kc][3], ad + (P_XLO - P_XHI));
        }

        #pragma unroll
        for (int m = 0; m < 3; m++) {
            uint32_t wbase = sb + P_WH + (uint32_t)(m * P_WSTRIDE);
            #pragma unroll
            for (int kc = 0; kc < 4; kc++) {
                #pragma unroll
                for (int ncp = 0; ncp < 4; ncp++) {
                    uint32_t ad = wbase + (uint32_t)((kc * 16 + krv) * 128)
                                + (((2 * ncp + vbit) ^ s7) << 4);
                    uint32_t bh0, bh1, bh2, bh3;
                    ldsm4t(bh0, bh1, bh2, bh3, ad);
                    int n = 2 * ncp;
                    mma16816h(a0[m][n], a1[m][n], a2[m][n], a3[m][n],
                              xh[kc][0], xh[kc][1], xh[kc][2], xh[kc][3], bh0, bh1);
                    mma16816h(a0[m][n], a1[m][n], a2[m][n], a3[m][n],
                              xl[kc][0], xl[kc][1], xl[kc][2], xl[kc][3], bh0, bh1);
                    mma16816h(a0[m][n+1], a1[m][n+1], a2[m][n+1], a3[m][n+1],
                              xh[kc][0], xh[kc][1], xh[kc][2], xh[kc][3], bh2, bh3);
                    mma16816h(a0[m][n+1], a1[m][n+1], a2[m][n+1], a3[m][n+1],
                              xl[kc][0], xl[kc][1], xl[kc][2], xl[kc][3], bh2, bh3);
                }
            }
        }
    }

    const int rA = mt * 128 + wrow + (lane >> 2);
    const int rB = rA + 8;

    #pragma unroll
    for (int m = 0; m < 3; m++) {
        float mu0 = 0.f, mu1 = 0.f, rs0 = 1.f, rs1 = 1.f;
        if (m < 2) {
            float sum0 = 0.f, sum1 = 0.f;
            #pragma unroll
            for (int nc = 0; nc < 8; nc++) {
                sum0 += a0[m][nc] + a1[m][nc];
                sum1 += a2[m][nc] + a3[m][nc];
            }
            sum0 += __shfl_xor_sync(0xffffffffu, sum0, 1);
            sum0 += __shfl_xor_sync(0xffffffffu, sum0, 2);
            sum1 += __shfl_xor_sync(0xffffffffu, sum1, 1);
            sum1 += __shfl_xor_sync(0xffffffffu, sum1, 2);
            mu0 = sum0 * (1.0f / 64.0f);
            mu1 = sum1 * (1.0f / 64.0f);
            float v0 = 0.f, v1 = 0.f;
            #pragma unroll
            for (int nc = 0; nc < 8; nc++) {
                float d00 = a0[m][nc] - mu0, d01 = a1[m][nc] - mu0;
                float d10 = a2[m][nc] - mu1, d11 = a3[m][nc] - mu1;
                v0 += d00 * d00 + d01 * d01;
                v1 += d10 * d10 + d11 * d11;
            }
            v0 += __shfl_xor_sync(0xffffffffu, v0, 1);
            v0 += __shfl_xor_sync(0xffffffffu, v0, 2);
            v1 += __shfl_xor_sync(0xffffffffu, v1, 1);
            v1 += __shfl_xor_sync(0xffffffffu, v1, 2);
            rs0 = rsqrtf(v0 * (1.0f / 64.0f) + 1e-5f);
            rs1 = rsqrtf(v1 * (1.0f / 64.0f) + 1e-5f);
        }

        uint32_t* g32 = (uint32_t*)((m == 0) ? g_qh : ((m == 1) ? g_kh : g_vh));
        #pragma unroll
        for (int nc = 0; nc < 8; nc++) {
            uint32_t hA = packhf((a0[m][nc] - mu0) * rs0, (a1[m][nc] - mu0) * rs0);
            uint32_t hB = packhf((a2[m][nc] - mu1) * rs1, (a3[m][nc] - mu1) * rs1);
            size_t iA = (size_t)rA * 32 + nc * 4 + (lane & 3);
            size_t iB = (size_t)rB * 32 + nc * 4 + (lane & 3);
            g32[iA] = hA;
            g32[iB] = hB;
        }
    }
}

// ===========================================================================
// Kernel 2: flash attention, fp16 mma, crossbar-optimized warp layout.
// Grid 128, 256 threads. Warps = 4 row-groups (32 q rows each, 2 m16 A-tiles)
// x 2 key-halves (64 keys of each 128-key tile). Each K/V ldsm feeds 4 mma
// -> 128 B smem per mma (half of R8). Fixed-reference softmax; key-half
// partials combined once in smem at the end.
// ===========================================================================
#define OFF_KHI 0
#define OFF_VHI 16384
#define TB      32768
#define NT      (S_ / 128)
#define ATTN_SMEM 65536
#define EP_OST   66                 // epilogue row stride (floats)
#define EP_LBASE 33792              // after 4 x 8448-byte o regions

__global__ __launch_bounds__(256) void attn_mma_kernel(float* __restrict__ out)
{
    extern __shared__ char smem[];
    const uint32_t sb = smem_u32(smem);
    const int tid  = threadIdx.x;
    const int warp = tid >> 5, lane = tid & 31;
    const int wg   = warp & 3;           // row group: 32 query rows
    const int half = warp >> 2;          // key half within each tile
    const int wrow = wg * 32;
    const int keyoff = half * 64;

    const int qbase = blockIdx.x * 128;
    const int b     = qbase / S_;

    // ---- stage Q tile into stage0 K area, grab 2 A-tiles of fragments ----
    {
        const uint4* qh4 = (const uint4*)((const char*)g_qh + (size_t)qbase * 128);
        #pragma unroll
        for (int j = 0; j < 4; j++) {
            int f = tid + j * 256;
            int r = f >> 3, c = f & 7;
            uint32_t so = r * 128 + ((c ^ (r & 7)) << 4);
            *(uint4*)(smem + OFF_KHI + so) = qh4[f];
        }
    }
    __syncthreads();

    uint32_t qf[2][4][4];
    #pragma unroll
    for (int t = 0; t < 2; t++) {
        int arow = wrow + t * 16 + (lane & 15);
        int as7  = arow & 7;
        #pragma unroll
        for (int kc = 0; kc < 4; kc++) {
            int c16 = 2 * kc + (lane >> 4);
            uint32_t ad = sb + OFF_KHI + arow * 128 + ((c16 ^ as7) << 4);
            ldsm4(qf[t][kc][0], qf[t][kc][1], qf[t][kc][2], qf[t][kc][3], ad);
        }
    }
    __syncthreads();

    const char* khB = (const char*)g_kh + (size_t)(b * S_) * 128;
    const char* vhB = (const char*)g_vh + (size_t)(b * S_) * 128;

    // prefetch tile 0 -> buf 0
    {
        #pragma unroll
        for (int j = 0; j < 4; j++) {
            int f = tid + j * 256;
            int r = f >> 3, c = f & 7;
            uint32_t so = r * 128 + ((c ^ (r & 7)) << 4);
            int gs = f * 16;
            CP_ASYNC16(sb + OFF_KHI + so, khB + gs);
            CP_ASYNC16(sb + OFF_VHI + so, vhB + gs);
        }
        CP_COMMIT();
    }

    float sa0[2][8], sa1[2][8], sa2[2][8], sa3[2][8];
    float oa0[2][8], oa1[2][8], oa2[2][8], oa3[2][8];
    #pragma unroll
    for (int t = 0; t < 2; t++)
        #pragma unroll
        for (int i = 0; i < 8; i++) { oa0[t][i]=0.f; oa1[t][i]=0.f; oa2[t][i]=0.f; oa3[t][i]=0.f; }
    float lq0[2] = {0.f, 0.f}, lq1[2] = {0.f, 0.f};

    const int s7   = lane & 7;
    const int krq  = (lane & 7) + ((lane >> 4) << 3);
    const int cbit = (lane >> 3) & 1;
    const int krv  = lane & 15;
    const int vbit = lane >> 4;
    const float C = 0.125f * 1.44269504088896f;   // exp(0.125 s) = 2^(s*C)

    for (int kt = 0; kt < NT; kt++) {
        __syncthreads();

        if (kt + 1 < NT) {
            uint32_t dst = sb + ((kt + 1) & 1) * TB;
            size_t gb = (size_t)((kt + 1) * 128) * 128;
            #pragma unroll
            for (int j = 0; j < 4; j++) {
                int f = tid + j * 256;
                int r = f >> 3, c = f & 7;
                uint32_t so = r * 128 + ((c ^ (r & 7)) << 4);
                size_t gs = gb + f * 16;
                CP_ASYNC16(dst + OFF_KHI + so, khB + gs);
                CP_ASYNC16(dst + OFF_VHI + so, vhB + gs);
            }
            CP_COMMIT();
            CP_WAIT(1);
        } else {
            CP_WAIT(0);
        }
        __syncthreads();

        const uint32_t bufb = sb + (kt & 1) * TB;

        // ---- S = Q K^T : 32 rows x 64 keys per warp; each ldsm -> 4 mma ----
        #pragma unroll
        for (int t = 0; t < 2; t++)
            #pragma unroll
            for (int i = 0; i < 8; i++) { sa0[t][i]=0.f; sa1[t][i]=0.f; sa2[t][i]=0.f; sa3[t][i]=0.f; }
        #pragma unroll
        for (int kc = 0; kc < 4; kc++) {
            #pragma unroll
            for (int ncp = 0; ncp < 4; ncp++) {
                uint32_t ad = bufb + OFF_KHI + (uint32_t)((keyoff + ncp * 16 + krq) * 128)
                            + (((2 * kc + cbit) ^ s7) << 4);
                uint32_t bh0, bh1, bh2, bh3;
                ldsm4(bh0, bh1, bh2, bh3, ad);
                int n = 2 * ncp;
                #pragma unroll
                for (int t = 0; t < 2; t++) {
                    mma16816h(sa0[t][n], sa1[t][n], sa2[t][n], sa3[t][n],
                              qf[t][kc][0], qf[t][kc][1], qf[t][kc][2], qf[t][kc][3], bh0, bh1);
                    mma16816h(sa0[t][n+1], sa1[t][n+1], sa2[t][n+1], sa3[t][n+1],
                              qf[t][kc][0], qf[t][kc][1], qf[t][kc][2], qf[t][kc][3], bh2, bh3);
                }
            }
        }

        // ---- p = exp2(s*C); accumulate l (fixed reference, no max) ----
        #pragma unroll
        for (int t = 0; t < 2; t++)
            #pragma unroll
            for (int i = 0; i < 8; i++) {
                sa0[t][i] = ex2f(sa0[t][i] * C); sa1[t][i] = ex2f(sa1[t][i] * C);
                sa2[t][i] = ex2f(sa2[t][i] * C); sa3[t][i] = ex2f(sa3[t][i] * C);
                lq0[t] += sa0[t][i] + sa1[t][i];
                lq1[t] += sa2[t][i] + sa3[t][i];
            }

        // ---- O += P V : each V ldsm -> 4 mma ----
        #pragma unroll
        for (int kc = 0; kc < 4; kc++) {
            uint32_t ph[2][4];
            #pragma unroll
            for (int t = 0; t < 2; t++) {
                ph[t][0] = packhf(sa0[t][2*kc],   sa1[t][2*kc]);
                ph[t][1] = packhf(sa2[t][2*kc],   sa3[t][2*kc]);
                ph[t][2] = packhf(sa0[t][2*kc+1], sa1[t][2*kc+1]);
                ph[t][3] = packhf(sa2[t][2*kc+1], sa3[t][2*kc+1]);
            }
            #pragma unroll
            for (int ncp = 0; ncp < 4; ncp++) {
                uint32_t ad = bufb + OFF_VHI + (uint32_t)((keyoff + kc * 16 + krv) * 128)
                            + (((2 * ncp + vbit) ^ s7) << 4);
                uint32_t bh0, bh1, bh2, bh3;
                ldsm4t(bh0, bh1, bh2, bh3, ad);
                int n = 2 * ncp;
                #pragma unroll
                for (int t = 0; t < 2; t++) {
                    mma16816h(oa0[t][n], oa1[t][n], oa2[t][n], oa3[t][n],
                              ph[t][0], ph[t][1], ph[t][2], ph[t][3], bh0, bh1);
                    mma16816h(oa0[t][n+1], oa1[t][n+1], oa2[t][n+1], oa3[t][n+1],
                              ph[t][0], ph[t][1], ph[t][2], ph[t][3], bh2, bh3);
                }
            }
        }
    }

    // ---- reduce l across quads (per row) ----
    #pragma unroll
    for (int t = 0; t < 2; t++) {
        lq0[t] += __shfl_xor_sync(0xffffffffu, lq0[t], 1);
        lq0[t] += __shfl_xor_sync(0xffffffffu, lq0[t], 2);
        lq1[t] += __shfl_xor_sync(0xffffffffu, lq1[t], 1);
        lq1[t] += __shfl_xor_sync(0xffffffffu, lq1[t], 2);
    }

    const int r   = lane >> 2;
    const int c2a = (lane & 3) * 2;

    __syncthreads();   // all warps done with K/V smem; reuse for combine

    if (half == 1) {
        // key-half 1 stages its partial o and l
        char* ob = smem + wg * 8448;
        #pragma unroll
        for (int t = 0; t < 2; t++) {
            #pragma unroll
            for (int nc = 0; nc < 8; nc++) {
                int row0 = t * 16 + r;
                int col  = 8 * nc + c2a;
                *(float2*)(ob + (size_t)(row0 * EP_OST + col) * 4) =
                    make_float2(oa0[t][nc], oa1[t][nc]);
                *(float2*)(ob + (size_t)((row0 + 8) * EP_OST + col) * 4) =
                    make_float2(oa2[t][nc], oa3[t][nc]);
            }
        }
        if ((lane & 3) == 0) {
            float* lb = (float*)(smem + EP_LBASE + wg * 128);
            #pragma unroll
            for (int t = 0; t < 2; t++) {
                lb[t * 16 + r]     = lq0[t];
                lb[t * 16 + r + 8] = lq1[t];
            }
        }
    }
    __syncthreads();

    if (half == 0) {
        const char*  ob = smem + wg * 8448;
        const float* lb = (const float*)(smem + EP_LBASE + wg * 128);
        float2* out2 = (float2*)out;
        #pragma unroll
        for (int t = 0; t < 2; t++) {
            float il0 = 1.0f / (lq0[t] + lb[t * 16 + r]);
            float il1 = 1.0f / (lq1[t] + lb[t * 16 + r + 8]);
            #pragma unroll
            for (int nc = 0; nc < 8; nc++) {
                int row0 = t * 16 + r;
                int col  = 8 * nc + c2a;
                float2 p = *(const float2*)(ob + (size_t)(row0 * EP_OST + col) * 4);
                float2 q = *(const float2*)(ob + (size_t)((row0 + 8) * EP_OST + col) * 4);
                size_t i_lo = ((size_t)(qbase + wrow + row0)     * 64 + col) >> 1;
                size_t i_hi = ((size_t)(qbase + wrow + row0 + 8) * 64 + col) >> 1;
                out2[i_lo] = make_float2((oa0[t][nc] + p.x) * il0, (oa1[t][nc] + p.y) * il0);
                out2[i_hi] = make_float2((oa2[t][nc] + q.x) * il1, (oa3[t][nc] + q.y) * il1);
            }
        }
    }
}

// ===========================================================================
// Launch
// ===========================================================================
extern "C" void kernel_launch(void* const* d_in, const int* in_sizes, int n_in,
                              void* d_out, int out_size)
{
    const float* X  = (const float*)d_in[0];
    const float* Wq = (const float*)d_in[1];
    const float* Wk = (const float*)d_in[2];
    const float* Wv = (const float*)d_in[3];
    float* out = (float*)d_out;

    dim3 gw(16, 3);
    split_w_kernel<<<gw, 256>>>(Wq, Wk, Wv);

    cudaFuncSetAttribute(proj_ln_kernel, cudaFuncAttributeMaxDynamicSharedMemorySize, PROJ_SMEM);
    proj_ln_kernel<<<NROWS / 128, 256, PROJ_SMEM>>>(X);

    cudaFuncSetAttribute(attn_mma_kernel, cudaFuncAttributeMaxDynamicSharedMemorySize, ATTN_SMEM);
    attn_mma_kernel<<<NROWS / 128, 256, ATTN_SMEM>>>(out);
}

// round 11
// speedup vs baseline: 1.6178x; 1.2718x over previous
#include <cuda_runtime.h>
#include <cuda_fp16.h>
#include <math.h>
#include <stdint.h>

// Problem shape: B=4, S=4096, D=1024, H=64
#define B_ 4
#define S_ 4096
#define D_ 1024
#define H_ 64
#define NROWS (B_ * S_)   // 16384

// Attention operands (fp16). Q pre-scaled by C = 0.125*log2(e) so the QK mma
// directly emits the exp2 argument. K, V unscaled.
__device__ __half g_qh[NROWS * H_];
__device__ __half g_kh[NROWS * H_];
__device__ __half g_vh[NROWS * H_];
// Pre-converted W (fp16) in per-64k-chunk swizzled tile layout (8KB per chunk).
__device__ __half g_wh[3][D_ * H_];

#define EXPC 0.18033688f   // 0.125 * log2(e)

// ===========================================================================
// helpers
// ===========================================================================
__device__ __forceinline__ uint32_t smem_u32(const void* p) {
    uint32_t a;
    asm("{ .reg .u64 t; cvta.to.shared.u64 t, %1; cvt.u32.u64 %0, t; }" : "=r"(a) : "l"(p));
    return a;
}
__device__ __forceinline__ uint32_t packhf(float a, float b) {
    uint32_t r;
    asm("cvt.rn.f16x2.f32 %0, %2, %1;" : "=r"(r) : "f"(a), "f"(b));
    return r;
}
__device__ __forceinline__ uint32_t pack2h(__half a, __half b) {
    return (uint32_t)__half_as_ushort(a) | ((uint32_t)__half_as_ushort(b) << 16);
}
__device__ __forceinline__ void split2h(float a, float b, uint32_t& hi, uint32_t& lo) {
    __half ha = __float2half_rn(a), hb = __float2half_rn(b);
    hi = pack2h(ha, hb);
    lo = packhf(a - __half2float(ha), b - __half2float(hb));
}
__device__ __forceinline__ uint32_t ex2h2(uint32_t x) {
    uint32_t r;
    asm("ex2.approx.f16x2 %0, %1;" : "=r"(r) : "r"(x));
    return r;
}

__device__ __forceinline__ void ldsm4(uint32_t& r0, uint32_t& r1, uint32_t& r2, uint32_t& r3, uint32_t addr) {
    asm volatile("ldmatrix.sync.aligned.m8n8.x4.shared.b16 {%0,%1,%2,%3}, [%4];"
        : "=r"(r0), "=r"(r1), "=r"(r2), "=r"(r3) : "r"(addr));
}
__device__ __forceinline__ void ldsm4t(uint32_t& r0, uint32_t& r1, uint32_t& r2, uint32_t& r3, uint32_t addr) {
    asm volatile("ldmatrix.sync.aligned.m8n8.x4.trans.shared.b16 {%0,%1,%2,%3}, [%4];"
        : "=r"(r0), "=r"(r1), "=r"(r2), "=r"(r3) : "r"(addr));
}
__device__ __forceinline__ void mma16816h(float& d0, float& d1, float& d2, float& d3,
                                           uint32_t a0, uint32_t a1, uint32_t a2, uint32_t a3,
                                           uint32_t b0, uint32_t b1) {
    asm volatile("mma.sync.aligned.m16n8k16.row.col.f32.f16.f16.f32 "
        "{%0,%1,%2,%3}, {%4,%5,%6,%7}, {%8,%9}, {%0,%1,%2,%3};"
        : "+f"(d0), "+f"(d1), "+f"(d2), "+f"(d3)
        : "r"(a0), "r"(a1), "r"(a2), "r"(a3), "r"(b0), "r"(b1));
}

#define CP_ASYNC16(dst, src) \
    asm volatile("cp.async.cg.shared.global [%0], [%1], 16;" :: "r"(dst), "l"(src))
#define CP_COMMIT() asm volatile("cp.async.commit_group;" ::: "memory")
#define CP_WAIT(n)  asm volatile("cp.async.wait_group %0;" :: "n"(n) : "memory")

// ===========================================================================
// Kernel 0: convert W matrices to fp16, per-chunk swizzled tiles.
// ===========================================================================
__global__ __launch_bounds__(256) void split_w_kernel(
    const float* __restrict__ Wq, const float* __restrict__ Wk, const float* __restrict__ Wv)
{
    const int ck = blockIdx.x, m = blockIdx.y, tid = threadIdx.x;
    const float4* W4 = (const float4*)((m == 0) ? Wq : ((m == 1) ? Wk : Wv));
    char* hiB = (char*)g_wh[m] + ck * 8192;
    #pragma unroll
    for (int j = 0; j < 4; j++) {
        int f = tid + j * 256;
        int r = f >> 4, c4 = f & 15;
        float4 v = W4[(size_t)(ck * 64 + r) * 16 + c4];
        uint32_t so = (uint32_t)(r * 128 + (((c4 >> 1) ^ (r & 7)) << 4) + (c4 & 1) * 8);
        *(uint32_t*)(hiB + so)     = packhf(v.x, v.y);
        *(uint32_t*)(hiB + so + 4) = packhf(v.z, v.w);
    }
}

// ===========================================================================
// Kernel 1: fused QKV projection + LayerNorm, fp16x2 (X hi/lo, W single).
// X register-prefetched one k-iter ahead to hide LDG latency.
// ===========================================================================
#define P_XHI 0
#define P_XLO 16384
#define P_WH  32768
#define P_WSTRIDE 8192
#define PROJ_SMEM (32768 + 3 * 8192)

__global__ __launch_bounds__(256) void proj_ln_kernel(const float* __restrict__ X)
{
    extern __shared__ char smem[];
    const uint32_t sb = smem_u32(smem);
    const int tid  = threadIdx.x;
    const int warp = tid >> 5, lane = tid & 31;
    const int wrow = warp * 16;
    const int mt   = blockIdx.x;

    float a0[3][8], a1[3][8], a2[3][8], a3[3][8];
    #pragma unroll
    for (int m = 0; m < 3; m++)
        #pragma unroll
        for (int nc = 0; nc < 8; nc++) { a0[m][nc]=0.f; a1[m][nc]=0.f; a2[m][nc]=0.f; a3[m][nc]=0.f; }

    const float4* X4 = (const float4*)X;

    const int arow = wrow + (lane & 15);
    const int as7  = arow & 7;
    const int abit = lane >> 4;
    const int krv  = lane & 15;
    const int vbit = lane >> 4;
    const int s7   = lane & 7;

    // prefetch X chunk 0 into registers
    float4 xv[8];
    #pragma unroll
    for (int j = 0; j < 8; j++) {
        int f = tid + j * 256;
        xv[j] = X4[(size_t)(mt * 128 + (f >> 4)) * 256 + (f & 15)];
    }

    for (int kk = 0; kk < D_; kk += 64) {
        __syncthreads();

        #pragma unroll
        for (int m = 0; m < 3; m++) {
            const char* srcH = (const char*)g_wh[m] + (kk >> 6) * 8192;
            #pragma unroll
            for (int j = 0; j < 2; j++) {
                int f16 = (tid + j * 256) * 16;
                CP_ASYNC16(sb + P_WH + (uint32_t)(m * P_WSTRIDE) + f16, srcH + f16);
            }
        }
        CP_COMMIT();

        // convert prefetched X chunk -> smem (fp16 hi/lo, swizzled)
        #pragma unroll
        for (int j = 0; j < 8; j++) {
            int f = tid + j * 256;
            int r = f >> 4, c4 = f & 15;
            float4 v = xv[j];
            uint32_t h0, l0, h1, l1;
            split2h(v.x, v.y, h0, l0);
            split2h(v.z, v.w, h1, l1);
            uint32_t so = (uint32_t)(r * 128 + (((c4 >> 1) ^ (r & 7)) << 4) + (c4 & 1) * 8);
            *(uint32_t*)(smem + P_XHI + so)     = h0;
            *(uint32_t*)(smem + P_XHI + so + 4) = h1;
            *(uint32_t*)(smem + P_XLO + so)     = l0;
            *(uint32_t*)(smem + P_XLO + so + 4) = l1;
        }
        // prefetch next X chunk (consumed next iteration; latency hidden by mma)
        if (kk + 64 < D_) {
            #pragma unroll
            for (int j = 0; j < 8; j++) {
                int f = tid + j * 256;
                xv[j] = X4[(size_t)(mt * 128 + (f >> 4)) * 256 + ((kk + 64) >> 2) + (f & 15)];
            }
        }
        CP_WAIT(0);
        __syncthreads();

        uint32_t xh[4][4], xl[4][4];
        #pragma unroll
        for (int kc = 0; kc < 4; kc++) {
            int c16 = 2 * kc + abit;
            uint32_t ad = sb + P_XHI + (uint32_t)(arow * 128) + ((c16 ^ as7) << 4);
            ldsm4(xh[kc][0], xh[kc][1], xh[kc][2], xh[kc][3], ad);
            ldsm4(xl[kc][0], xl[kc][1], xl[kc][2], xl[kc][3], ad + (P_XLO - P_XHI));
        }

        #pragma unroll
        for (int m = 0; m < 3; m++) {
            uint32_t wbase = sb + P_WH + (uint32_t)(m * P_WSTRIDE);
            #pragma unroll
            for (int kc = 0; kc < 4; kc++) {
                #pragma unroll
                for (int ncp = 0; ncp < 4; ncp++) {
                    uint32_t ad = wbase + (uint32_t)((kc * 16 + krv) * 128)
                                + (((2 * ncp + vbit) ^ s7) << 4);
                    uint32_t bh0, bh1, bh2, bh3;
                    ldsm4t(bh0, bh1, bh2, bh3, ad);
                    int n = 2 * ncp;
                    mma16816h(a0[m][n], a1[m][n], a2[m][n], a3[m][n],
                              xh[kc][0], xh[kc][1], xh[kc][2], xh[kc][3], bh0, bh1);
                    mma16816h(a0[m][n], a1[m][n], a2[m][n], a3[m][n],
                              xl[kc][0], xl[kc][1], xl[kc][2], xl[kc][3], bh0, bh1);
                    mma16816h(a0[m][n+1], a1[m][n+1], a2[m][n+1], a3[m][n+1],
                              xh[kc][0], xh[kc][1], xh[kc][2], xh[kc][3], bh2, bh3);
                    mma16816h(a0[m][n+1], a1[m][n+1], a2[m][n+1], a3[m][n+1],
                              xl[kc][0], xl[kc][1], xl[kc][2], xl[kc][3], bh2, bh3);
                }
            }
        }
    }

    const int rA = mt * 128 + wrow + (lane >> 2);
    const int rB = rA + 8;

    #pragma unroll
    for (int m = 0; m < 3; m++) {
        float mu0 = 0.f, mu1 = 0.f, rs0 = 1.f, rs1 = 1.f;
        if (m < 2) {
            float sum0 = 0.f, sum1 = 0.f;
            #pragma unroll
            for (int nc = 0; nc < 8; nc++) {
                sum0 += a0[m][nc] + a1[m][nc];
                sum1 += a2[m][nc] + a3[m][nc];
            }
            sum0 += __shfl_xor_sync(0xffffffffu, sum0, 1);
            sum0 += __shfl_xor_sync(0xffffffffu, sum0, 2);
            sum1 += __shfl_xor_sync(0xffffffffu, sum1, 1);
            sum1 += __shfl_xor_sync(0xffffffffu, sum1, 2);
            mu0 = sum0 * (1.0f / 64.0f);
            mu1 = sum1 * (1.0f / 64.0f);
            float v0 = 0.f, v1 = 0.f;
            #pragma unroll
            for (int nc = 0; nc < 8; nc++) {
                float d00 = a0[m][nc] - mu0, d01 = a1[m][nc] - mu0;
                float d10 = a2[m][nc] - mu1, d11 = a3[m][nc] - mu1;
                v0 += d00 * d00 + d01 * d01;
                v1 += d10 * d10 + d11 * d11;
            }
            v0 += __shfl_xor_sync(0xffffffffu, v0, 1);
            v0 += __shfl_xor_sync(0xffffffffu, v0, 2);
            v1 += __shfl_xor_sync(0xffffffffu, v1, 1);
            v1 += __shfl_xor_sync(0xffffffffu, v1, 2);
            rs0 = rsqrtf(v0 * (1.0f / 64.0f) + 1e-5f);
            rs1 = rsqrtf(v1 * (1.0f / 64.0f) + 1e-5f);
        }
        // fold exp2 constant into Q so attn's QK mma emits the ex2 argument
        if (m == 0) { rs0 *= EXPC; rs1 *= EXPC; }

        uint32_t* g32 = (uint32_t*)((m == 0) ? g_qh : ((m == 1) ? g_kh : g_vh));
        #pragma unroll
        for (int nc = 0; nc < 8; nc++) {
            uint32_t hA = packhf((a0[m][nc] - mu0) * rs0, (a1[m][nc] - mu0) * rs0);
            uint32_t hB = packhf((a2[m][nc] - mu1) * rs1, (a3[m][nc] - mu1) * rs1);
            size_t iA = (size_t)rA * 32 + nc * 4 + (lane & 3);
            size_t iB = (size_t)rB * 32 + nc * 4 + (lane & 3);
            g32[iA] = hA;
            g32[iB] = hB;
        }
    }
}

// ===========================================================================
// Kernel 2: flash attention, fp16 mma; ex2.approx.f16x2 softmax, l-sum via
// ones-B tensor mma (no FADD chains, no shuffles). Fixed-reference softmax.
// ===========================================================================
#define OFF_KHI 0
#define OFF_VHI 16384
#define TB      32768
#define NT      (S_ / 128)
#define ATTN_SMEM (2 * TB)
#define ONESH2  0x3C003C00u   // fp16x2 {1.0, 1.0}

__global__ __launch_bounds__(256) void attn_mma_kernel(float* __restrict__ out)
{
    extern __shared__ char smem[];
    const uint32_t sb = smem_u32(smem);
    const int tid  = threadIdx.x;
    const int warp = tid >> 5, lane = tid & 31;
    const int wrow = warp * 16;

    const int qbase = blockIdx.x * 128;
    const int b     = qbase / S_;

    // ---- stage Q into buf0 (K area), grab A fragments ----
    {
        const uint4* qh4 = (const uint4*)((const char*)g_qh + (size_t)qbase * 128);
        #pragma unroll
        for (int j = 0; j < 4; j++) {
            int f = tid + j * 256;
            int r = f >> 3, c = f & 7;
            uint32_t so = r * 128 + ((c ^ (r & 7)) << 4);
            *(uint4*)(smem + OFF_KHI + so) = qh4[f];
        }
    }
    __syncthreads();

    uint32_t qh[4][4];
    {
        int arow = wrow + (lane & 15);
        int as7  = arow & 7;
        #pragma unroll
        for (int kc = 0; kc < 4; kc++) {
            int c16 = 2 * kc + (lane >> 4);
            uint32_t ad = sb + OFF_KHI + arow * 128 + ((c16 ^ as7) << 4);
            ldsm4(qh[kc][0], qh[kc][1], qh[kc][2], qh[kc][3], ad);
        }
    }
    __syncthreads();

    const char* khB = (const char*)g_kh + (size_t)(b * S_) * 128;
    const char* vhB = (const char*)g_vh + (size_t)(b * S_) * 128;

    // prefetch tile 0 -> buf 0
    {
        #pragma unroll
        for (int j = 0; j < 4; j++) {
            int f = tid + j * 256;
            int r = f >> 3, c = f & 7;
            uint32_t so = r * 128 + ((c ^ (r & 7)) << 4);
            int gs = f * 16;
            CP_ASYNC16(sb + OFF_KHI + so, khB + gs);
            CP_ASYNC16(sb + OFF_VHI + so, vhB + gs);
        }
        CP_COMMIT();
    }

    float s0[16], s1[16], s2[16], s3[16];
    float o0[8], o1[8], o2[8], o3[8];
    float la0 = 0.f, la1 = 0.f, la2 = 0.f, la3 = 0.f;   // l accumulators (ones-mma)
    #pragma unroll
    for (int i = 0; i < 8; i++) { o0[i] = 0.f; o1[i] = 0.f; o2[i] = 0.f; o3[i] = 0.f; }

    const int s7   = lane & 7;
    const int krq  = (lane & 7) + ((lane >> 4) << 3);
    const int cbit = (lane >> 3) & 1;
    const int krv  = lane & 15;
    const int vbit = lane >> 4;

    for (int kt = 0; kt < NT; kt++) {
        __syncthreads();

        if (kt + 1 < NT) {
            uint32_t dst = sb + ((kt + 1) & 1) * TB;
            size_t gb = (size_t)((kt + 1) * 128) * 128;
            #pragma unroll
            for (int j = 0; j < 4; j++) {
                int f = tid + j * 256;
                int r = f >> 3, c = f & 7;
                uint32_t so = r * 128 + ((c ^ (r & 7)) << 4);
                size_t gs = gb + f * 16;
                CP_ASYNC16(dst + OFF_KHI + so, khB + gs);
                CP_ASYNC16(dst + OFF_VHI + so, vhB + gs);
            }
            CP_COMMIT();
            CP_WAIT(1);
        } else {
            CP_WAIT(0);
        }
        __syncthreads();

        const uint32_t bufb = sb + (kt & 1) * TB;

        // ---- S' = Q' K^T  (Q pre-scaled; S' is the exp2 argument) ----
        #pragma unroll
        for (int i = 0; i < 16; i++) { s0[i] = 0.f; s1[i] = 0.f; s2[i] = 0.f; s3[i] = 0.f; }
        #pragma unroll
        for (int kc = 0; kc < 4; kc++) {
            #pragma unroll
            for (int ncp = 0; ncp < 8; ncp++) {
                uint32_t ad = bufb + OFF_KHI + (uint32_t)(ncp * 16 + krq) * 128
                            + (((2 * kc + cbit) ^ s7) << 4);
                uint32_t bh0, bh1, bh2, bh3;
                ldsm4(bh0, bh1, bh2, bh3, ad);
                int n = 2 * ncp;
                mma16816h(s0[n], s1[n], s2[n], s3[n], qh[kc][0], qh[kc][1], qh[kc][2], qh[kc][3], bh0, bh1);
                mma16816h(s0[n+1], s1[n+1], s2[n+1], s3[n+1], qh[kc][0], qh[kc][1], qh[kc][2], qh[kc][3], bh2, bh3);
            }
        }

        // ---- p = ex2.f16x2(s'), packed directly into PV A-fragment regs ----
        uint32_t p01[16], p23[16];
        #pragma unroll
        for (int i = 0; i < 16; i++) {
            p01[i] = ex2h2(packhf(s0[i], s1[i]));
            p23[i] = ex2h2(packhf(s2[i], s3[i]));
        }

        // ---- O += P V ; l += P @ ones (tensor-pipe row sums) ----
        #pragma unroll
        for (int kc = 0; kc < 8; kc++) {
            uint32_t ph0 = p01[2*kc], ph1 = p23[2*kc];
            uint32_t ph2 = p01[2*kc+1], ph3 = p23[2*kc+1];
            mma16816h(la0, la1, la2, la3, ph0, ph1, ph2, ph3, ONESH2, ONESH2);
            #pragma unroll
            for (int ncp = 0; ncp < 4; ncp++) {
                uint32_t ad = bufb + OFF_VHI + (uint32_t)(kc * 16 + krv) * 128
                            + (((2 * ncp + vbit) ^ s7) << 4);
                uint32_t bh0, bh1, bh2, bh3;
                ldsm4t(bh0, bh1, bh2, bh3, ad);
                int n = 2 * ncp;
                mma16816h(o0[n], o1[n], o2[n], o3[n], ph0, ph1, ph2, ph3, bh0, bh1);
                mma16816h(o0[n+1], o1[n+1], o2[n+1], o3[n+1], ph0, ph1, ph2, ph3, bh2, bh3);
            }
        }
    }

    // la0 = full row sum (row r), la2 = row r+8 — identical across the quad.
    const float il0 = 1.0f / la0, il1 = 1.0f / la2;
    const int r  = lane >> 2;
    const int c2 = (lane & 3) * 2;
    float2* out2 = (float2*)out;
    #pragma unroll
    for (int nc = 0; nc < 8; nc++) {
        size_t i_lo = ((size_t)(qbase + wrow + r)     * 64 + 8 * nc + c2) >> 1;
        size_t i_hi = ((size_t)(qbase + wrow + r + 8) * 64 + 8 * nc + c2) >> 1;
        out2[i_lo] = make_float2(o0[nc] * il0, o1[nc] * il0);
        out2[i_hi] = make_float2(o2[nc] * il1, o3[nc] * il1);
    }
}

// ===========================================================================
// Launch
// ===========================================================================
extern "C" void kernel_launch(void* const* d_in, const int* in_sizes, int n_in,
                              void* d_out, int out_size)
{
    const float* X  = (const float*)d_in[0];
    const float* Wq = (const float*)d_in[1];
    const float* Wk = (const float*)d_in[2];
    const float* Wv = (const float*)d_in[3];
    float* out = (float*)d_out;

    dim3 gw(16, 3);
    split_w_kernel<<<gw, 256>>>(Wq, Wk, Wv);

    cudaFuncSetAttribute(proj_ln_kernel, cudaFuncAttributeMaxDynamicSharedMemorySize, PROJ_SMEM);
    proj_ln_kernel<<<NROWS / 128, 256, PROJ_SMEM>>>(X);

    cudaFuncSetAttribute(attn_mma_kernel, cudaFuncAttributeMaxDynamicSharedMemorySize, ATTN_SMEM);
    attn_mma_kernel<<<NROWS / 128, 256, ATTN_SMEM>>>(out);
}

// round 12
// speedup vs baseline: 1.6230x; 1.0032x over previous
#include <cuda_runtime.h>
#include <cuda_fp16.h>
#include <math.h>
#include <stdint.h>

// Problem shape: B=4, S=4096, D=1024, H=64
#define B_ 4
#define S_ 4096
#define D_ 1024
#define H_ 64
#define NROWS (B_ * S_)   // 16384

// Attention operands (fp16). Q pre-scaled by C = 0.125*log2(e) so the QK mma
// directly emits the exp2 argument. K, V unscaled.
__device__ __half g_qh[NROWS * H_];
__device__ __half g_kh[NROWS * H_];
__device__ __half g_vh[NROWS * H_];
// Pre-converted W (fp16) in per-64k-chunk swizzled tile layout (8KB per chunk).
__device__ __half g_wh[3][D_ * H_];

#define EXPC 0.18033688f   // 0.125 * log2(e)

// ===========================================================================
// helpers
// ===========================================================================
__device__ __forceinline__ uint32_t smem_u32(const void* p) {
    uint32_t a;
    asm("{ .reg .u64 t; cvta.to.shared.u64 t, %1; cvt.u32.u64 %0, t; }" : "=r"(a) : "l"(p));
    return a;
}
__device__ __forceinline__ uint32_t packhf(float a, float b) {
    uint32_t r;
    asm("cvt.rn.f16x2.f32 %0, %2, %1;" : "=r"(r) : "f"(a), "f"(b));
    return r;
}
__device__ __forceinline__ uint32_t pack2h(__half a, __half b) {
    return (uint32_t)__half_as_ushort(a) | ((uint32_t)__half_as_ushort(b) << 16);
}
__device__ __forceinline__ void split2h(float a, float b, uint32_t& hi, uint32_t& lo) {
    __half ha = __float2half_rn(a), hb = __float2half_rn(b);
    hi = pack2h(ha, hb);
    lo = packhf(a - __half2float(ha), b - __half2float(hb));
}
__device__ __forceinline__ uint32_t ex2h2(uint32_t x) {
    uint32_t r;
    asm("ex2.approx.f16x2 %0, %1;" : "=r"(r) : "r"(x));
    return r;
}

__device__ __forceinline__ void ldsm4(uint32_t& r0, uint32_t& r1, uint32_t& r2, uint32_t& r3, uint32_t addr) {
    asm volatile("ldmatrix.sync.aligned.m8n8.x4.shared.b16 {%0,%1,%2,%3}, [%4];"
        : "=r"(r0), "=r"(r1), "=r"(r2), "=r"(r3) : "r"(addr));
}
__device__ __forceinline__ void ldsm4t(uint32_t& r0, uint32_t& r1, uint32_t& r2, uint32_t& r3, uint32_t addr) {
    asm volatile("ldmatrix.sync.aligned.m8n8.x4.trans.shared.b16 {%0,%1,%2,%3}, [%4];"
        : "=r"(r0), "=r"(r1), "=r"(r2), "=r"(r3) : "r"(addr));
}
__device__ __forceinline__ void mma16816h(float& d0, float& d1, float& d2, float& d3,
                                           uint32_t a0, uint32_t a1, uint32_t a2, uint32_t a3,
                                           uint32_t b0, uint32_t b1) {
    asm volatile("mma.sync.aligned.m16n8k16.row.col.f32.f16.f16.f32 "
        "{%0,%1,%2,%3}, {%4,%5,%6,%7}, {%8,%9}, {%0,%1,%2,%3};"
        : "+f"(d0), "+f"(d1), "+f"(d2), "+f"(d3)
        : "r"(a0), "r"(a1), "r"(a2), "r"(a3), "r"(b0), "r"(b1));
}

#define CP_ASYNC16(dst, src) \
    asm volatile("cp.async.cg.shared.global [%0], [%1], 16;" :: "r"(dst), "l"(src))
#define CP_COMMIT() asm volatile("cp.async.commit_group;" ::: "memory")
#define CP_WAIT(n)  asm volatile("cp.async.wait_group %0;" :: "n"(n) : "memory")

// ===========================================================================
// Kernel 0: convert W matrices to fp16, per-chunk swizzled tiles.
// ===========================================================================
__global__ __launch_bounds__(256) void split_w_kernel(
    const float* __restrict__ Wq, const float* __restrict__ Wk, const float* __restrict__ Wv)
{
    const int ck = blockIdx.x, m = blockIdx.y, tid = threadIdx.x;
    const float4* W4 = (const float4*)((m == 0) ? Wq : ((m == 1) ? Wk : Wv));
    char* hiB = (char*)g_wh[m] + ck * 8192;
    #pragma unroll
    for (int j = 0; j < 4; j++) {
        int f = tid + j * 256;
        int r = f >> 4, c4 = f & 15;
        float4 v = W4[(size_t)(ck * 64 + r) * 16 + c4];
        uint32_t so = (uint32_t)(r * 128 + (((c4 >> 1) ^ (r & 7)) << 4) + (c4 & 1) * 8);
        *(uint32_t*)(hiB + so)     = packhf(v.x, v.y);
        *(uint32_t*)(hiB + so + 4) = packhf(v.z, v.w);
    }
}

// ===========================================================================
// Kernel 1: fused QKV projection + LayerNorm, fp16x2 (X hi/lo, W single).
// X register-prefetched one k-iter ahead to hide LDG latency.
// ===========================================================================
#define P_XHI 0
#define P_XLO 16384
#define P_WH  32768
#define P_WSTRIDE 8192
#define PROJ_SMEM (32768 + 3 * 8192)

__global__ __launch_bounds__(256) void proj_ln_kernel(const float* __restrict__ X)
{
    extern __shared__ char smem[];
    const uint32_t sb = smem_u32(smem);
    const int tid  = threadIdx.x;
    const int warp = tid >> 5, lane = tid & 31;
    const int wrow = warp * 16;
    const int mt   = blockIdx.x;

    float a0[3][8], a1[3][8], a2[3][8], a3[3][8];
    #pragma unroll
    for (int m = 0; m < 3; m++)
        #pragma unroll
        for (int nc = 0; nc < 8; nc++) { a0[m][nc]=0.f; a1[m][nc]=0.f; a2[m][nc]=0.f; a3[m][nc]=0.f; }

    const float4* X4 = (const float4*)X;

    const int arow = wrow + (lane & 15);
    const int as7  = arow & 7;
    const int abit = lane >> 4;
    const int krv  = lane & 15;
    const int vbit = lane >> 4;
    const int s7   = lane & 7;

    // prefetch X chunk 0 into registers
    float4 xv[8];
    #pragma unroll
    for (int j = 0; j < 8; j++) {
        int f = tid + j * 256;
        xv[j] = X4[(size_t)(mt * 128 + (f >> 4)) * 256 + (f & 15)];
    }

    for (int kk = 0; kk < D_; kk += 64) {
        __syncthreads();

        #pragma unroll
        for (int m = 0; m < 3; m++) {
            const char* srcH = (const char*)g_wh[m] + (kk >> 6) * 8192;
            #pragma unroll
            for (int j = 0; j < 2; j++) {
                int f16 = (tid + j * 256) * 16;
                CP_ASYNC16(sb + P_WH + (uint32_t)(m * P_WSTRIDE) + f16, srcH + f16);
            }
        }
        CP_COMMIT();

        // convert prefetched X chunk -> smem (fp16 hi/lo, swizzled)
        #pragma unroll
        for (int j = 0; j < 8; j++) {
            int f = tid + j * 256;
            int r = f >> 4, c4 = f & 15;
            float4 v = xv[j];
            uint32_t h0, l0, h1, l1;
            split2h(v.x, v.y, h0, l0);
            split2h(v.z, v.w, h1, l1);
            uint32_t so = (uint32_t)(r * 128 + (((c4 >> 1) ^ (r & 7)) << 4) + (c4 & 1) * 8);
            *(uint32_t*)(smem + P_XHI + so)     = h0;
            *(uint32_t*)(smem + P_XHI + so + 4) = h1;
            *(uint32_t*)(smem + P_XLO + so)     = l0;
            *(uint32_t*)(smem + P_XLO + so + 4) = l1;
        }
        // prefetch next X chunk (consumed next iteration; latency hidden by mma)
        if (kk + 64 < D_) {
            #pragma unroll
            for (int j = 0; j < 8; j++) {
                int f = tid + j * 256;
                xv[j] = X4[(size_t)(mt * 128 + (f >> 4)) * 256 + ((kk + 64) >> 2) + (f & 15)];
            }
        }
        CP_WAIT(0);
        __syncthreads();

        uint32_t xh[4][4], xl[4][4];
        #pragma unroll
        for (int kc = 0; kc < 4; kc++) {
            int c16 = 2 * kc + abit;
            uint32_t ad = sb + P_XHI + (uint32_t)(arow * 128) + ((c16 ^ as7) << 4);
            ldsm4(xh[kc][0], xh[kc][1], xh[kc][2], xh[kc][3], ad);
            ldsm4(xl[kc][0], xl[kc][1], xl[kc][2], xl[kc][3], ad + (P_XLO - P_XHI));
        }

        #pragma unroll
        for (int m = 0; m < 3; m++) {
            uint32_t wbase = sb + P_WH + (uint32_t)(m * P_WSTRIDE);
            #pragma unroll
            for (int kc = 0; kc < 4; kc++) {
                #pragma unroll
                for (int ncp = 0; ncp < 4; ncp++) {
                    uint32_t ad = wbase + (uint32_t)((kc * 16 + krv) * 128)
                                + (((2 * ncp + vbit) ^ s7) << 4);
                    uint32_t bh0, bh1, bh2, bh3;
                    ldsm4t(bh0, bh1, bh2, bh3, ad);
                    int n = 2 * ncp;
                    mma16816h(a0[m][n], a1[m][n], a2[m][n], a3[m][n],
                              xh[kc][0], xh[kc][1], xh[kc][2], xh[kc][3], bh0, bh1);
                    mma16816h(a0[m][n], a1[m][n], a2[m][n], a3[m][n],
                              xl[kc][0], xl[kc][1], xl[kc][2], xl[kc][3], bh0, bh1);
                    mma16816h(a0[m][n+1], a1[m][n+1], a2[m][n+1], a3[m][n+1],
                              xh[kc][0], xh[kc][1], xh[kc][2], xh[kc][3], bh2, bh3);
                    mma16816h(a0[m][n+1], a1[m][n+1], a2[m][n+1], a3[m][n+1],
                              xl[kc][0], xl[kc][1], xl[kc][2], xl[kc][3], bh2, bh3);
                }
            }
        }
    }

    const int rA = mt * 128 + wrow + (lane >> 2);
    const int rB = rA + 8;

    #pragma unroll
    for (int m = 0; m < 3; m++) {
        float mu0 = 0.f, mu1 = 0.f, rs0 = 1.f, rs1 = 1.f;
        if (m < 2) {
            float sum0 = 0.f, sum1 = 0.f;
            #pragma unroll
            for (int nc = 0; nc < 8; nc++) {
                sum0 += a0[m][nc] + a1[m][nc];
                sum1 += a2[m][nc] + a3[m][nc];
            }
            sum0 += __shfl_xor_sync(0xffffffffu, sum0, 1);
            sum0 += __shfl_xor_sync(0xffffffffu, sum0, 2);
            sum1 += __shfl_xor_sync(0xffffffffu, sum1, 1);
            sum1 += __shfl_xor_sync(0xffffffffu, sum1, 2);
            mu0 = sum0 * (1.0f / 64.0f);
            mu1 = sum1 * (1.0f / 64.0f);
            float v0 = 0.f, v1 = 0.f;
            #pragma unroll
            for (int nc = 0; nc < 8; nc++) {
                float d00 = a0[m][nc] - mu0, d01 = a1[m][nc] - mu0;
                float d10 = a2[m][nc] - mu1, d11 = a3[m][nc] - mu1;
                v0 += d00 * d00 + d01 * d01;
                v1 += d10 * d10 + d11 * d11;
            }
            v0 += __shfl_xor_sync(0xffffffffu, v0, 1);
            v0 += __shfl_xor_sync(0xffffffffu, v0, 2);
            v1 += __shfl_xor_sync(0xffffffffu, v1, 1);
            v1 += __shfl_xor_sync(0xffffffffu, v1, 2);
            rs0 = rsqrtf(v0 * (1.0f / 64.0f) + 1e-5f);
            rs1 = rsqrtf(v1 * (1.0f / 64.0f) + 1e-5f);
        }
        // fold exp2 constant into Q so attn's QK mma emits the ex2 argument
        if (m == 0) { rs0 *= EXPC; rs1 *= EXPC; }

        uint32_t* g32 = (uint32_t*)((m == 0) ? g_qh : ((m == 1) ? g_kh : g_vh));
        #pragma unroll
        for (int nc = 0; nc < 8; nc++) {
            uint32_t hA = packhf((a0[m][nc] - mu0) * rs0, (a1[m][nc] - mu0) * rs0);
            uint32_t hB = packhf((a2[m][nc] - mu1) * rs1, (a3[m][nc] - mu1) * rs1);
            size_t iA = (size_t)rA * 32 + nc * 4 + (lane & 3);
            size_t iB = (size_t)rB * 32 + nc * 4 + (lane & 3);
            g32[iA] = hA;
            g32[iB] = hB;
        }
    }
}

// ===========================================================================
// Kernel 2: flash attention, fp16 mma; ex2.approx.f16x2 softmax, l-sum via
// ones-B tensor mma (no FADD chains, no shuffles). Fixed-reference softmax.
// ===========================================================================
#define OFF_KHI 0
#define OFF_VHI 16384
#define TB      32768
#define NT      (S_ / 128)
#define ATTN_SMEM (2 * TB)
#define ONESH2  0x3C003C00u   // fp16x2 {1.0, 1.0}

__global__ __launch_bounds__(256) void attn_mma_kernel(float* __restrict__ out)
{
    extern __shared__ char smem[];
    const uint32_t sb = smem_u32(smem);
    const int tid  = threadIdx.x;
    const int warp = tid >> 5, lane = tid & 31;
    const int wrow = warp * 16;

    const int qbase = blockIdx.x * 128;
    const int b     = qbase / S_;

    // ---- stage Q into buf0 (K area), grab A fragments ----
    {
        const uint4* qh4 = (const uint4*)((const char*)g_qh + (size_t)qbase * 128);
        #pragma unroll
        for (int j = 0; j < 4; j++) {
            int f = tid + j * 256;
            int r = f >> 3, c = f & 7;
            uint32_t so = r * 128 + ((c ^ (r & 7)) << 4);
            *(uint4*)(smem + OFF_KHI + so) = qh4[f];
        }
    }
    __syncthreads();

    uint32_t qh[4][4];
    {
        int arow = wrow + (lane & 15);
        int as7  = arow & 7;
        #pragma unroll
        for (int kc = 0; kc < 4; kc++) {
            int c16 = 2 * kc + (lane >> 4);
            uint32_t ad = sb + OFF_KHI + arow * 128 + ((c16 ^ as7) << 4);
            ldsm4(qh[kc][0], qh[kc][1], qh[kc][2], qh[kc][3], ad);
        }
    }
    __syncthreads();

    const char* khB = (const char*)g_kh + (size_t)(b * S_) * 128;
    const char* vhB = (const char*)g_vh + (size_t)(b * S_) * 128;

    // prefetch tile 0 -> buf 0
    {
        #pragma unroll
        for (int j = 0; j < 4; j++) {
            int f = tid + j * 256;
            int r = f >> 3, c = f & 7;
            uint32_t so = r * 128 + ((c ^ (r & 7)) << 4);
            int gs = f * 16;
            CP_ASYNC16(sb + OFF_KHI + so, khB + gs);
            CP_ASYNC16(sb + OFF_VHI + so, vhB + gs);
        }
        CP_COMMIT();
    }

    float s0[16], s1[16], s2[16], s3[16];
    float o0[8], o1[8], o2[8], o3[8];
    float la0 = 0.f, la1 = 0.f, la2 = 0.f, la3 = 0.f;   // l accumulators (ones-mma)
    #pragma unroll
    for (int i = 0; i < 8; i++) { o0[i] = 0.f; o1[i] = 0.f; o2[i] = 0.f; o3[i] = 0.f; }

    const int s7   = lane & 7;
    const int krq  = (lane & 7) + ((lane >> 4) << 3);
    const int cbit = (lane >> 3) & 1;
    const int krv  = lane & 15;
    const int vbit = lane >> 4;

    for (int kt = 0; kt < NT; kt++) {
        __syncthreads();

        if (kt + 1 < NT) {
            uint32_t dst = sb + ((kt + 1) & 1) * TB;
            size_t gb = (size_t)((kt + 1) * 128) * 128;
            #pragma unroll
            for (int j = 0; j < 4; j++) {
                int f = tid + j * 256;
                int r = f >> 3, c = f & 7;
                uint32_t so = r * 128 + ((c ^ (r & 7)) << 4);
                size_t gs = gb + f * 16;
                CP_ASYNC16(dst + OFF_KHI + so, khB + gs);
                CP_ASYNC16(dst + OFF_VHI + so, vhB + gs);
            }
            CP_COMMIT();
            CP_WAIT(1);
        } else {
            CP_WAIT(0);
        }
        __syncthreads();

        const uint32_t bufb = sb + (kt & 1) * TB;

        // ---- S' = Q' K^T  (Q pre-scaled; S' is the exp2 argument) ----
        #pragma unroll
        for (int i = 0; i < 16; i++) { s0[i] = 0.f; s1[i] = 0.f; s2[i] = 0.f; s3[i] = 0.f; }
        #pragma unroll
        for (int kc = 0; kc < 4; kc++) {
            #pragma unroll
            for (int ncp = 0; ncp < 8; ncp++) {
                uint32_t ad = bufb + OFF_KHI + (uint32_t)(ncp * 16 + krq) * 128
                            + (((2 * kc + cbit) ^ s7) << 4);
                uint32_t bh0, bh1, bh2, bh3;
                ldsm4(bh0, bh1, bh2, bh3, ad);
                int n = 2 * ncp;
                mma16816h(s0[n], s1[n], s2[n], s3[n], qh[kc][0], qh[kc][1], qh[kc][2], qh[kc][3], bh0, bh1);
                mma16816h(s0[n+1], s1[n+1], s2[n+1], s3[n+1], qh[kc][0], qh[kc][1], qh[kc][2], qh[kc][3], bh2, bh3);
            }
        }

        // ---- p = ex2.f16x2(s'), packed directly into PV A-fragment regs ----
        uint32_t p01[16], p23[16];
        #pragma unroll
        for (int i = 0; i < 16; i++) {
            p01[i] = ex2h2(packhf(s0[i], s1[i]));
            p23[i] = ex2h2(packhf(s2[i], s3[i]));
        }

        // ---- O += P V ; l += P @ ones (tensor-pipe row sums) ----
        #pragma unroll
        for (int kc = 0; kc < 8; kc++) {
            uint32_t ph0 = p01[2*kc], ph1 = p23[2*kc];
            uint32_t ph2 = p01[2*kc+1], ph3 = p23[2*kc+1];
            mma16816h(la0, la1, la2, la3, ph0, ph1, ph2, ph3, ONESH2, ONESH2);
            #pragma unroll
            for (int ncp = 0; ncp < 4; ncp++) {
                uint32_t ad = bufb + OFF_VHI + (uint32_t)(kc * 16 + krv) * 128
                            + (((2 * ncp + vbit) ^ s7) << 4);
                uint32_t bh0, bh1, bh2, bh3;
                ldsm4t(bh0, bh1, bh2, bh3, ad);
                int n = 2 * ncp;
                mma16816h(o0[n], o1[n], o2[n], o3[n], ph0, ph1, ph2, ph3, bh0, bh1);
                mma16816h(o0[n+1], o1[n+1], o2[n+1], o3[n+1], ph0, ph1, ph2, ph3, bh2, bh3);
            }
        }
    }

    // la0 = full row sum (row r), la2 = row r+8 — identical across the quad.
    const float il0 = 1.0f / la0, il1 = 1.0f / la2;
    const int r  = lane >> 2;
    const int c2 = (lane & 3) * 2;
    float2* out2 = (float2*)out;
    #pragma unroll
    for (int nc = 0; nc < 8; nc++) {
        size_t i_lo = ((size_t)(qbase + wrow + r)     * 64 + 8 * nc + c2) >> 1;
        size_t i_hi = ((size_t)(qbase + wrow + r + 8) * 64 + 8 * nc + c2) >> 1;
        out2[i_lo] = make_float2(o0[nc] * il0, o1[nc] * il0);
        out2[i_hi] = make_float2(o2[nc] * il1, o3[nc] * il1);
    }
}

// ===========================================================================
// Launch
// ===========================================================================
extern "C" void kernel_launch(void* const* d_in, const int* in_sizes, int n_in,
                              void* d_out, int out_size)
{
    const float* X  = (const float*)d_in[0];
    const float* Wq = (const float*)d_in[1];
    const float* Wk = (const float*)d_in[2];
    const float* Wv = (const float*)d_in[3];
    float* out = (float*)d_out;

    dim3 gw(16, 3);
    split_w_kernel<<<gw, 256>>>(Wq, Wk, Wv);

    cudaFuncSetAttribute(proj_ln_kernel, cudaFuncAttributeMaxDynamicSharedMemorySize, PROJ_SMEM);
    proj_ln_kernel<<<NROWS / 128, 256, PROJ_SMEM>>>(X);

    cudaFuncSetAttribute(attn_mma_kernel, cudaFuncAttributeMaxDynamicSharedMemorySize, ATTN_SMEM);
    attn_mma_kernel<<<NROWS / 128, 256, ATTN_SMEM>>>(out);
}

// round 13
// speedup vs baseline: 1.8803x; 1.1585x over previous
#include <cuda_runtime.h>
#include <cuda_fp16.h>
#include <math.h>
#include <stdint.h>

// Problem shape: B=4, S=4096, D=1024, H=64
#define B_ 4
#define S_ 4096
#define D_ 1024
#define H_ 64
#define NROWS (B_ * S_)   // 16384

// Attention operands (fp16). Q pre-scaled by C = 0.125*log2(e) so the QK mma
// directly emits the exp2 argument. K, V unscaled.
__device__ __half g_qh[NROWS * H_];
__device__ __half g_kh[NROWS * H_];
__device__ __half g_vh[NROWS * H_];
// Pre-converted W (fp16) in per-64k-chunk swizzled tile layout (8KB per chunk).
__device__ __half g_wh[3][D_ * H_];

#define EXPC 0.18033688f   // 0.125 * log2(e)

// ===========================================================================
// helpers
// ===========================================================================
__device__ __forceinline__ uint32_t smem_u32(const void* p) {
    uint32_t a;
    asm("{ .reg .u64 t; cvta.to.shared.u64 t, %1; cvt.u32.u64 %0, t; }" : "=r"(a) : "l"(p));
    return a;
}
__device__ __forceinline__ uint32_t packhf(float a, float b) {
    uint32_t r;
    asm("cvt.rn.f16x2.f32 %0, %2, %1;" : "=r"(r) : "f"(a), "f"(b));
    return r;
}
__device__ __forceinline__ uint32_t ex2h2(uint32_t x) {
    uint32_t r;
    asm("ex2.approx.f16x2 %0, %1;" : "=r"(r) : "r"(x));
    return r;
}

__device__ __forceinline__ void ldsm4(uint32_t& r0, uint32_t& r1, uint32_t& r2, uint32_t& r3, uint32_t addr) {
    asm volatile("ldmatrix.sync.aligned.m8n8.x4.shared.b16 {%0,%1,%2,%3}, [%4];"
        : "=r"(r0), "=r"(r1), "=r"(r2), "=r"(r3) : "r"(addr));
}
__device__ __forceinline__ void ldsm4t(uint32_t& r0, uint32_t& r1, uint32_t& r2, uint32_t& r3, uint32_t addr) {
    asm volatile("ldmatrix.sync.aligned.m8n8.x4.trans.shared.b16 {%0,%1,%2,%3}, [%4];"
        : "=r"(r0), "=r"(r1), "=r"(r2), "=r"(r3) : "r"(addr));
}
__device__ __forceinline__ void mma16816h(float& d0, float& d1, float& d2, float& d3,
                                           uint32_t a0, uint32_t a1, uint32_t a2, uint32_t a3,
                                           uint32_t b0, uint32_t b1) {
    asm volatile("mma.sync.aligned.m16n8k16.row.col.f32.f16.f16.f32 "
        "{%0,%1,%2,%3}, {%4,%5,%6,%7}, {%8,%9}, {%0,%1,%2,%3};"
        : "+f"(d0), "+f"(d1), "+f"(d2), "+f"(d3)
        : "r"(a0), "r"(a1), "r"(a2), "r"(a3), "r"(b0), "r"(b1));
}

#define CP_ASYNC16(dst, src) \
    asm volatile("cp.async.cg.shared.global [%0], [%1], 16;" :: "r"(dst), "l"(src))
#define CP_COMMIT() asm volatile("cp.async.commit_group;" ::: "memory")
#define CP_WAIT(n)  asm volatile("cp.async.wait_group %0;" :: "n"(n) : "memory")

// ===========================================================================
// Kernel 0: convert W matrices to fp16, per-chunk swizzled tiles.
// ===========================================================================
__global__ __launch_bounds__(256) void split_w_kernel(
    const float* __restrict__ Wq, const float* __restrict__ Wk, const float* __restrict__ Wv)
{
    const int ck = blockIdx.x, m = blockIdx.y, tid = threadIdx.x;
    const float4* W4 = (const float4*)((m == 0) ? Wq : ((m == 1) ? Wk : Wv));
    char* hiB = (char*)g_wh[m] + ck * 8192;
    #pragma unroll
    for (int j = 0; j < 4; j++) {
        int f = tid + j * 256;
        int r = f >> 4, c4 = f & 15;
        float4 v = W4[(size_t)(ck * 64 + r) * 16 + c4];
        uint32_t so = (uint32_t)(r * 128 + (((c4 >> 1) ^ (r & 7)) << 4) + (c4 & 1) * 8);
        *(uint32_t*)(hiB + so)     = packhf(v.x, v.y);
        *(uint32_t*)(hiB + so + 4) = packhf(v.z, v.w);
    }
}

// ===========================================================================
// Kernel 1: fused QKV projection + LayerNorm, single-pass fp16 (X hi only).
// X register-prefetched one k-iter ahead to hide LDG latency.
// ===========================================================================
#define P_XH  0
#define P_WH  16384
#define P_WSTRIDE 8192
#define PROJ_SMEM (16384 + 3 * 8192)

__global__ __launch_bounds__(256) void proj_ln_kernel(const float* __restrict__ X)
{
    extern __shared__ char smem[];
    const uint32_t sb = smem_u32(smem);
    const int tid  = threadIdx.x;
    const int warp = tid >> 5, lane = tid & 31;
    const int wrow = warp * 16;
    const int mt   = blockIdx.x;

    float a0[3][8], a1[3][8], a2[3][8], a3[3][8];
    #pragma unroll
    for (int m = 0; m < 3; m++)
        #pragma unroll
        for (int nc = 0; nc < 8; nc++) { a0[m][nc]=0.f; a1[m][nc]=0.f; a2[m][nc]=0.f; a3[m][nc]=0.f; }

    const float4* X4 = (const float4*)X;

    const int arow = wrow + (lane & 15);
    const int as7  = arow & 7;
    const int abit = lane >> 4;
    const int krv  = lane & 15;
    const int vbit = lane >> 4;
    const int s7   = lane & 7;

    // prefetch X chunk 0 into registers
    float4 xv[8];
    #pragma unroll
    for (int j = 0; j < 8; j++) {
        int f = tid + j * 256;
        xv[j] = X4[(size_t)(mt * 128 + (f >> 4)) * 256 + (f & 15)];
    }

    for (int kk = 0; kk < D_; kk += 64) {
        __syncthreads();

        #pragma unroll
        for (int m = 0; m < 3; m++) {
            const char* srcH = (const char*)g_wh[m] + (kk >> 6) * 8192;
            #pragma unroll
            for (int j = 0; j < 2; j++) {
                int f16 = (tid + j * 256) * 16;
                CP_ASYNC16(sb + P_WH + (uint32_t)(m * P_WSTRIDE) + f16, srcH + f16);
            }
        }
        CP_COMMIT();

        // convert prefetched X chunk -> smem (fp16, swizzled)
        #pragma unroll
        for (int j = 0; j < 8; j++) {
            int f = tid + j * 256;
            int r = f >> 4, c4 = f & 15;
            float4 v = xv[j];
            uint32_t so = (uint32_t)(r * 128 + (((c4 >> 1) ^ (r & 7)) << 4) + (c4 & 1) * 8);
            *(uint32_t*)(smem + P_XH + so)     = packhf(v.x, v.y);
            *(uint32_t*)(smem + P_XH + so + 4) = packhf(v.z, v.w);
        }
        // prefetch next X chunk (consumed next iteration; latency hidden by mma)
        if (kk + 64 < D_) {
            #pragma unroll
            for (int j = 0; j < 8; j++) {
                int f = tid + j * 256;
                xv[j] = X4[(size_t)(mt * 128 + (f >> 4)) * 256 + ((kk + 64) >> 2) + (f & 15)];
            }
        }
        CP_WAIT(0);
        __syncthreads();

        uint32_t xh[4][4];
        #pragma unroll
        for (int kc = 0; kc < 4; kc++) {
            int c16 = 2 * kc + abit;
            uint32_t ad = sb + P_XH + (uint32_t)(arow * 128) + ((c16 ^ as7) << 4);
            ldsm4(xh[kc][0], xh[kc][1], xh[kc][2], xh[kc][3], ad);
        }

        #pragma unroll
        for (int m = 0; m < 3; m++) {
            uint32_t wbase = sb + P_WH + (uint32_t)(m * P_WSTRIDE);
            #pragma unroll
            for (int kc = 0; kc < 4; kc++) {
                #pragma unroll
                for (int ncp = 0; ncp < 4; ncp++) {
                    uint32_t ad = wbase + (uint32_t)((kc * 16 + krv) * 128)
                                + (((2 * ncp + vbit) ^ s7) << 4);
                    uint32_t bh0, bh1, bh2, bh3;
                    ldsm4t(bh0, bh1, bh2, bh3, ad);
                    int n = 2 * ncp;
                    mma16816h(a0[m][n], a1[m][n], a2[m][n], a3[m][n],
                              xh[kc][0], xh[kc][1], xh[kc][2], xh[kc][3], bh0, bh1);
                    mma16816h(a0[m][n+1], a1[m][n+1], a2[m][n+1], a3[m][n+1],
                              xh[kc][0], xh[kc][1], xh[kc][2], xh[kc][3], bh2, bh3);
                }
            }
        }
    }

    const int rA = mt * 128 + wrow + (lane >> 2);
    const int rB = rA + 8;

    #pragma unroll
    for (int m = 0; m < 3; m++) {
        float mu0 = 0.f, mu1 = 0.f, rs0 = 1.f, rs1 = 1.f;
        if (m < 2) {
            float sum0 = 0.f, sum1 = 0.f;
            #pragma unroll
            for (int nc = 0; nc < 8; nc++) {
                sum0 += a0[m][nc] + a1[m][nc];
                sum1 += a2[m][nc] + a3[m][nc];
            }
            sum0 += __shfl_xor_sync(0xffffffffu, sum0, 1);
            sum0 += __shfl_xor_sync(0xffffffffu, sum0, 2);
            sum1 += __shfl_xor_sync(0xffffffffu, sum1, 1);
            sum1 += __shfl_xor_sync(0xffffffffu, sum1, 2);
            mu0 = sum0 * (1.0f / 64.0f);
            mu1 = sum1 * (1.0f / 64.0f);
            float v0 = 0.f, v1 = 0.f;
            #pragma unroll
            for (int nc = 0; nc < 8; nc++) {
                float d00 = a0[m][nc] - mu0, d01 = a1[m][nc] - mu0;
                float d10 = a2[m][nc] - mu1, d11 = a3[m][nc] - mu1;
                v0 += d00 * d00 + d01 * d01;
                v1 += d10 * d10 + d11 * d11;
            }
            v0 += __shfl_xor_sync(0xffffffffu, v0, 1);
            v0 += __shfl_xor_sync(0xffffffffu, v0, 2);
            v1 += __shfl_xor_sync(0xffffffffu, v1, 1);
            v1 += __shfl_xor_sync(0xffffffffu, v1, 2);
            rs0 = rsqrtf(v0 * (1.0f / 64.0f) + 1e-5f);
            rs1 = rsqrtf(v1 * (1.0f / 64.0f) + 1e-5f);
        }
        // fold exp2 constant into Q so attn's QK mma emits the ex2 argument
        if (m == 0) { rs0 *= EXPC; rs1 *= EXPC; }

        uint32_t* g32 = (uint32_t*)((m == 0) ? g_qh : ((m == 1) ? g_kh : g_vh));
        #pragma unroll
        for (int nc = 0; nc < 8; nc++) {
            uint32_t hA = packhf((a0[m][nc] - mu0) * rs0, (a1[m][nc] - mu0) * rs0);
            uint32_t hB = packhf((a2[m][nc] - mu1) * rs1, (a3[m][nc] - mu1) * rs1);
            size_t iA = (size_t)rA * 32 + nc * 4 + (lane & 3);
            size_t iB = (size_t)rB * 32 + nc * 4 + (lane & 3);
            g32[iA] = hA;
            g32[iB] = hB;
        }
    }
}

// ===========================================================================
// Kernel 2: flash attention, fp16 mma; ex2.approx.f16x2 softmax, l-sum via
// ones-B tensor mma. Fixed-reference softmax. (unchanged from R12)
// ===========================================================================
#define OFF_KHI 0
#define OFF_VHI 16384
#define TB      32768
#define NT      (S_ / 128)
#define ATTN_SMEM (2 * TB)
#define ONESH2  0x3C003C00u   // fp16x2 {1.0, 1.0}

__global__ __launch_bounds__(256) void attn_mma_kernel(float* __restrict__ out)
{
    extern __shared__ char smem[];
    const uint32_t sb = smem_u32(smem);
    const int tid  = threadIdx.x;
    const int warp = tid >> 5, lane = tid & 31;
    const int wrow = warp * 16;

    const int qbase = blockIdx.x * 128;
    const int b     = qbase / S_;

    // ---- stage Q into buf0 (K area), grab A fragments ----
    {
        const uint4* qh4 = (const uint4*)((const char*)g_qh + (size_t)qbase * 128);
        #pragma unroll
        for (int j = 0; j < 4; j++) {
            int f = tid + j * 256;
            int r = f >> 3, c = f & 7;
            uint32_t so = r * 128 + ((c ^ (r & 7)) << 4);
            *(uint4*)(smem + OFF_KHI + so) = qh4[f];
        }
    }
    __syncthreads();

    uint32_t qh[4][4];
    {
        int arow = wrow + (lane & 15);
        int as7  = arow & 7;
        #pragma unroll
        for (int kc = 0; kc < 4; kc++) {
            int c16 = 2 * kc + (lane >> 4);
            uint32_t ad = sb + OFF_KHI + arow * 128 + ((c16 ^ as7) << 4);
            ldsm4(qh[kc][0], qh[kc][1], qh[kc][2], qh[kc][3], ad);
        }
    }
    __syncthreads();

    const char* khB = (const char*)g_kh + (size_t)(b * S_) * 128;
    const char* vhB = (const char*)g_vh + (size_t)(b * S_) * 128;

    // prefetch tile 0 -> buf 0
    {
        #pragma unroll
        for (int j = 0; j < 4; j++) {
            int f = tid + j * 256;
            int r = f >> 3, c = f & 7;
            uint32_t so = r * 128 + ((c ^ (r & 7)) << 4);
            int gs = f * 16;
            CP_ASYNC16(sb + OFF_KHI + so, khB + gs);
            CP_ASYNC16(sb + OFF_VHI + so, vhB + gs);
        }
        CP_COMMIT();
    }

    float s0[16], s1[16], s2[16], s3[16];
    float o0[8], o1[8], o2[8], o3[8];
    float la0 = 0.f, la1 = 0.f, la2 = 0.f, la3 = 0.f;   // l accumulators (ones-mma)
    #pragma unroll
    for (int i = 0; i < 8; i++) { o0[i] = 0.f; o1[i] = 0.f; o2[i] = 0.f; o3[i] = 0.f; }

    const int s7   = lane & 7;
    const int krq  = (lane & 7) + ((lane >> 4) << 3);
    const int cbit = (lane >> 3) & 1;
    const int krv  = lane & 15;
    const int vbit = lane >> 4;

    for (int kt = 0; kt < NT; kt++) {
        __syncthreads();

        if (kt + 1 < NT) {
            uint32_t dst = sb + ((kt + 1) & 1) * TB;
            size_t gb = (size_t)((kt + 1) * 128) * 128;
            #pragma unroll
            for (int j = 0; j < 4; j++) {
                int f = tid + j * 256;
                int r = f >> 3, c = f & 7;
                uint32_t so = r * 128 + ((c ^ (r & 7)) << 4);
                size_t gs = gb + f * 16;
                CP_ASYNC16(dst + OFF_KHI + so, khB + gs);
                CP_ASYNC16(dst + OFF_VHI + so, vhB + gs);
            }
            CP_COMMIT();
            CP_WAIT(1);
        } else {
            CP_WAIT(0);
        }
        __syncthreads();

        const uint32_t bufb = sb + (kt & 1) * TB;

        // ---- S' = Q' K^T  (Q pre-scaled; S' is the exp2 argument) ----
        #pragma unroll
        for (int i = 0; i < 16; i++) { s0[i] = 0.f; s1[i] = 0.f; s2[i] = 0.f; s3[i] = 0.f; }
        #pragma unroll
        for (int kc = 0; kc < 4; kc++) {
            #pragma unroll
            for (int ncp = 0; ncp < 8; ncp++) {
                uint32_t ad = bufb + OFF_KHI + (uint32_t)(ncp * 16 + krq) * 128
                            + (((2 * kc + cbit) ^ s7) << 4);
                uint32_t bh0, bh1, bh2, bh3;
                ldsm4(bh0, bh1, bh2, bh3, ad);
                int n = 2 * ncp;
                mma16816h(s0[n], s1[n], s2[n], s3[n], qh[kc][0], qh[kc][1], qh[kc][2], qh[kc][3], bh0, bh1);
                mma16816h(s0[n+1], s1[n+1], s2[n+1], s3[n+1], qh[kc][0], qh[kc][1], qh[kc][2], qh[kc][3], bh2, bh3);
            }
        }

        // ---- p = ex2.f16x2(s'), packed directly into PV A-fragment regs ----
        uint32_t p01[16], p23[16];
        #pragma unroll
        for (int i = 0; i < 16; i++) {
            p01[i] = ex2h2(packhf(s0[i], s1[i]));
            p23[i] = ex2h2(packhf(s2[i], s3[i]));
        }

        // ---- O += P V ; l += P @ ones (tensor-pipe row sums) ----
        #pragma unroll
        for (int kc = 0; kc < 8; kc++) {
            uint32_t ph0 = p01[2*kc], ph1 = p23[2*kc];
            uint32_t ph2 = p01[2*kc+1], ph3 = p23[2*kc+1];
            mma16816h(la0, la1, la2, la3, ph0, ph1, ph2, ph3, ONESH2, ONESH2);
            #pragma unroll
            for (int ncp = 0; ncp < 4; ncp++) {
                uint32_t ad = bufb + OFF_VHI + (uint32_t)(kc * 16 + krv) * 128
                            + (((2 * ncp + vbit) ^ s7) << 4);
                uint32_t bh0, bh1, bh2, bh3;
                ldsm4t(bh0, bh1, bh2, bh3, ad);
                int n = 2 * ncp;
                mma16816h(o0[n], o1[n], o2[n], o3[n], ph0, ph1, ph2, ph3, bh0, bh1);
                mma16816h(o0[n+1], o1[n+1], o2[n+1], o3[n+1], ph0, ph1, ph2, ph3, bh2, bh3);
            }
        }
    }

    // la0 = full row sum (row r), la2 = row r+8 — identical across the quad.
    const float il0 = 1.0f / la0, il1 = 1.0f / la2;
    const int r  = lane >> 2;
    const int c2 = (lane & 3) * 2;
    float2* out2 = (float2*)out;
    #pragma unroll
    for (int nc = 0; nc < 8; nc++) {
        size_t i_lo = ((size_t)(qbase + wrow + r)     * 64 + 8 * nc + c2) >> 1;
        size_t i_hi = ((size_t)(qbase + wrow + r + 8) * 64 + 8 * nc + c2) >> 1;
        out2[i_lo] = make_float2(o0[nc] * il0, o1[nc] * il0);
        out2[i_hi] = make_float2(o2[nc] * il1, o3[nc] * il1);
    }
}

// ===========================================================================
// Launch
// ===========================================================================
extern "C" void kernel_launch(void* const* d_in, const int* in_sizes, int n_in,
                              void* d_out, int out_size)
{
    const float* X  = (const float*)d_in[0];
    const float* Wq = (const float*)d_in[1];
    const float* Wk = (const float*)d_in[2];
    const float* Wv = (const float*)d_in[3];
    float* out = (float*)d_out;

    dim3 gw(16, 3);
    split_w_kernel<<<gw, 256>>>(Wq, Wk, Wv);

    cudaFuncSetAttribute(proj_ln_kernel, cudaFuncAttributeMaxDynamicSharedMemorySize, PROJ_SMEM);
    proj_ln_kernel<<<NROWS / 128, 256, PROJ_SMEM>>>(X);

    cudaFuncSetAttribute(attn_mma_kernel, cudaFuncAttributeMaxDynamicSharedMemorySize, ATTN_SMEM);
    attn_mma_kernel<<<NROWS / 128, 256, ATTN_SMEM>>>(out);
}